// round 12
// baseline (speedup 1.0000x reference)
#include <cuda_runtime.h>
#include <cuda_bf16.h>
#include <math.h>
#include <stdint.h>

// Problem constants
#define Bsz 8
#define SEQ 1024
#define EMB 1024
#define NH  16
#define HS  64
#define M_TOT (Bsz * SEQ)   // 8192

// Scratch layouts:
//  g_qu, g_ku : [BH][S][64 u32] bf16 hi/lo pair-packed rows (Q pre-scaled);
//               pair p = k-values (2p, 2p+1)  [attn S-phase layout]
//  g_v       : [BH][tile jt][d][t]  V transposed per 64-token tile, tf32-rna'd
//  g_att     : [B,S][1024 u32] bf16 hi/lo pair-packed, pair j = (d, d+8)
//              within each 16-group of d  [proj A operand]
//  g_xr/g_wt/g_wpr : bf16 hi/lo pair-packed GEMM operands, pair j = (k, k+8)
//              within each 16-group of k
__device__ uint32_t g_qu[Bsz * NH * SEQ * 64];
__device__ uint32_t g_ku[Bsz * NH * SEQ * 64];
__device__ float g_v[Bsz * NH * SEQ * HS];
__device__ uint32_t g_att[M_TOT * EMB];
__device__ uint32_t g_wt[3 * EMB * EMB];
__device__ uint32_t g_xr[M_TOT * EMB];
__device__ uint32_t g_wpr[EMB * EMB];

// ---------------------------------------------------------------------------
// Helpers
// ---------------------------------------------------------------------------
__device__ __forceinline__ uint32_t smem_u32(const void* p) {
    uint32_t a;
    asm("{ .reg .u64 t; cvta.to.shared.u64 t, %1; cvt.u32.u64 %0, t; }" : "=r"(a) : "l"(p));
    return a;
}
__device__ __forceinline__ float tf32_rna(float x) {
    uint32_t u;
    asm("cvt.rna.tf32.f32 %0, %1;" : "=r"(u) : "f"(x));
    return __uint_as_float(u);
}
// Split (x,y) into bf16 hi/lo: {hi_pack, lo_pack}; low half of each = x.
__device__ __forceinline__ uint2 bf16_split_pack(float x, float y) {
    __nv_bfloat16 hx = __float2bfloat16(x);
    __nv_bfloat16 hy = __float2bfloat16(y);
    float lx = x - __bfloat162float(hx);
    float ly = y - __bfloat162float(hy);
    __nv_bfloat162 hp = __halves2bfloat162(hx, hy);
    __nv_bfloat162 lp = __halves2bfloat162(__float2bfloat16(lx), __float2bfloat16(ly));
    uint2 r;
    r.x = *(uint32_t*)&hp;
    r.y = *(uint32_t*)&lp;
    return r;
}
// Packed-row u32 slot for pair j (0..7) within a 16-u32 block:
// uint4 at slot 4c holds [hi(j=c), lo, hi(j=c+4), lo].
__device__ __forceinline__ int uslot(int j) {
    return (j & 3) * 4 + ((j >> 2) << 1);
}
#define CP_ASYNC16(dst, src) \
    asm volatile("cp.async.cg.shared.global [%0], [%1], 16;" :: "r"(dst), "l"(src))
#define CP_COMMIT() asm volatile("cp.async.commit_group;" ::: "memory")
#define CP_WAIT(n)  asm volatile("cp.async.wait_group %0;" :: "n"(n) : "memory")

__device__ __forceinline__ void mma_tf32(float* d, const uint32_t* a, const uint32_t* b) {
    asm volatile(
        "mma.sync.aligned.m16n8k8.row.col.f32.tf32.tf32.f32 "
        "{%0,%1,%2,%3}, {%4,%5,%6,%7}, {%8,%9}, {%0,%1,%2,%3};"
        : "+f"(d[0]), "+f"(d[1]), "+f"(d[2]), "+f"(d[3])
        : "r"(a[0]), "r"(a[1]), "r"(a[2]), "r"(a[3]), "r"(b[0]), "r"(b[1]));
}
__device__ __forceinline__ void mma_bf16(float* d, const uint32_t* a, const uint32_t* b) {
    asm volatile(
        "mma.sync.aligned.m16n8k16.row.col.f32.bf16.bf16.f32 "
        "{%0,%1,%2,%3}, {%4,%5,%6,%7}, {%8,%9}, {%0,%1,%2,%3};"
        : "+f"(d[0]), "+f"(d[1]), "+f"(d[2]), "+f"(d[3])
        : "r"(a[0]), "r"(a[1]), "r"(a[2]), "r"(a[3]), "r"(b[0]), "r"(b[1]));
}

// ---------------------------------------------------------------------------
// Prep: bf16 hi/lo pair-pack (pairs (j, j+8) within 16-groups). 16 vals/thread.
// ---------------------------------------------------------------------------
__global__ __launch_bounds__(256)
void round_pack_kernel(const float* __restrict__ in, uint32_t* __restrict__ out) {
    size_t base = ((size_t)blockIdx.x * 256 + threadIdx.x) * 16;
    float v[16];
#pragma unroll
    for (int i = 0; i < 4; ++i)
        *(float4*)&v[i * 4] = *(const float4*)&in[base + i * 4];
#pragma unroll
    for (int j = 0; j < 8; ++j) {
        uint2 pk = bf16_split_pack(v[j], v[j + 8]);
        *(uint2*)&out[base + uslot(j)] = pk;
    }
}

// Transpose QKV weights -> g_wt[mat][j=h*64+d][e packed (e,e+8)-pairs].
__global__ __launch_bounds__(256)
void wt_transpose(const float* __restrict__ Wq,
                  const float* __restrict__ Wk,
                  const float* __restrict__ Wv) {
    __shared__ float t[64][65];
    const int tid = threadIdx.x;
    const int et = blockIdx.x;
    const int h  = blockIdx.y;
    const int mat = blockIdx.z;
    const float* W = (mat == 0) ? Wq : (mat == 1) ? Wk : Wv;
    const float* src = W + (size_t)h * (EMB * HS) + (size_t)(et * 64) * HS;
    uint32_t* out = g_wt + (size_t)mat * (EMB * EMB);

    for (int i = tid; i < 64 * 64; i += 256) {
        int e = i >> 6, d = i & 63;
        t[e][d] = src[(size_t)e * HS + d];
    }
    __syncthreads();
    for (int i = tid; i < 64 * 32; i += 256) {
        int d = i >> 5, idx = i & 31;
        int b = idx >> 3, j = idx & 7;
        uint2 pk = bf16_split_pack(t[b * 16 + j][d], t[b * 16 + j + 8][d]);
        *(uint2*)&out[(size_t)(h * 64 + d) * EMB + et * 64 + b * 16 + uslot(j)] = pk;
    }
}

// ---------------------------------------------------------------------------
// double-bf16 GEMM core: C[128,128] = A @ B^T (3-term hi/lo, m16n8k16).
// Operands: packed u32 rows. Smem rows stride 48 u32 (mod-32 = 16 ->
// conflict-free uint4 phases). 2-stage, K-chunk 32 (2 k16 blocks).
// ---------------------------------------------------------------------------
#define GLD 48
#define TILE_U (128 * GLD)                 // u32 per tile
#define STAGE_BYTES (2 * TILE_U * 4)       // A+B = 49152
#define MMA_SMEM_BYTES (2 * STAGE_BYTES)   // 98304
#define NCHUNK (EMB / 32)

__device__ __forceinline__ void gemm_load_chunk(uint32_t base, int buf, int kc,
                                                const uint32_t* __restrict__ Ag,
                                                const uint32_t* __restrict__ Bg,
                                                int m0, int n0, int tid) {
    uint32_t a_s = base + (uint32_t)buf * STAGE_BYTES;
    uint32_t b_s = a_s + TILE_U * 4;
    const uint32_t* ap = Ag + (size_t)m0 * EMB + kc * 32;
    const uint32_t* bp = Bg + (size_t)n0 * EMB + kc * 32;
#pragma unroll
    for (int i = 0; i < 4; ++i) {
        int idx = i * 256 + tid;
        int row = idx >> 3, c = idx & 7;
        CP_ASYNC16(a_s + (uint32_t)(row * GLD + c * 4) * 4, ap + (size_t)row * EMB + c * 4);
    }
#pragma unroll
    for (int i = 0; i < 4; ++i) {
        int idx = i * 256 + tid;
        int row = idx >> 3, c = idx & 7;
        CP_ASYNC16(b_s + (uint32_t)(row * GLD + c * 4) * 4, bp + (size_t)row * EMB + c * 4);
    }
    CP_COMMIT();
}

__device__ __forceinline__ void gemm_mainloop(char* smraw, uint32_t base,
                                              const uint32_t* __restrict__ Ag,
                                              const uint32_t* __restrict__ Bg,
                                              int m0, int n0,
                                              float acc[4][4][4]) {
    const int tid = threadIdx.x;
    const int wid = tid >> 5, lane = tid & 31;
    const int wm = wid & 1, wn = wid >> 1;
    const int r4 = lane >> 2, c4 = lane & 3;

    gemm_load_chunk(base, 0, 0, Ag, Bg, m0, n0, tid);
    gemm_load_chunk(base, 1, 1, Ag, Bg, m0, n0, tid);

    for (int kc = 0; kc < NCHUNK; ++kc) {
        if (kc + 1 < NCHUNK) { CP_WAIT(1); } else { CP_WAIT(0); }
        __syncthreads();

        const uint32_t* As = (const uint32_t*)(smraw + (size_t)(kc & 1) * STAGE_BYTES);
        const uint32_t* Bs = As + TILE_U;

#pragma unroll
        for (int kb = 0; kb < 2; ++kb) {
            uint4 bv[4];
#pragma unroll
            for (int nt = 0; nt < 4; ++nt)
                bv[nt] = *(const uint4*)&Bs[(wn * 32 + nt * 8 + r4) * GLD + kb * 16 + c4 * 4];
#pragma unroll
            for (int mt = 0; mt < 4; ++mt) {
                int ra = (wm * 64 + mt * 16 + r4) * GLD + kb * 16 + c4 * 4;
                uint4 q0 = *(const uint4*)&As[ra];
                uint4 q1 = *(const uint4*)&As[ra + 8 * GLD];
                uint32_t Ah[4] = {q0.x, q1.x, q0.z, q1.z};
                uint32_t Al[4] = {q0.y, q1.y, q0.w, q1.w};
#pragma unroll
                for (int nt = 0; nt < 4; ++nt) {
                    uint32_t Bh[2] = {bv[nt].x, bv[nt].z};
                    uint32_t Bl[2] = {bv[nt].y, bv[nt].w};
                    mma_bf16(acc[mt][nt], Ah, Bh);
                    mma_bf16(acc[mt][nt], Ah, Bl);
                    mma_bf16(acc[mt][nt], Al, Bh);
                }
            }
        }
        __syncthreads();
        if (kc + 2 < NCHUNK)
            gemm_load_chunk(base, kc & 1, kc + 2, Ag, Bg, m0, n0, tid);
    }
}

// ---------------------------------------------------------------------------
// Kernel 1: QKV projection; epilogue emits bf16-packed Q/K rows (pair (2p,2p+1))
// and tf32 V transposed per tile.
// ---------------------------------------------------------------------------
__global__ __launch_bounds__(256)
void qkv_mma(void) {
    extern __shared__ char sm[];
    uint32_t base = smem_u32(sm);
    const int tid = threadIdx.x;
    const int wid = tid >> 5, lane = tid & 31;
    const int wm = wid & 1, wn = wid >> 1;
    const int r4 = lane >> 2, c4 = lane & 3;
    const int mat = blockIdx.x >> 3;
    const int n0 = (blockIdx.x & 7) * 128;
    const int m0 = blockIdx.y * 128;
    const uint32_t* Bg = g_wt + (size_t)mat * (EMB * EMB);

    float acc[4][4][4] = {};
    gemm_mainloop(sm, base, g_xr, Bg, m0, n0, acc);

    const float qscale = (mat == 0) ? 0.125f : 1.0f;
#pragma unroll
    for (int mt = 0; mt < 4; ++mt) {
#pragma unroll
        for (int nt = 0; nt < 4; ++nt) {
            int n = n0 + wn * 32 + nt * 8 + c4 * 2;
            int h_ = n >> 6, d_ = n & 63;
#pragma unroll
            for (int rr = 0; rr < 2; ++rr) {
                int m = m0 + wm * 64 + mt * 16 + r4 + rr * 8;
                int b_ = m >> 10, s_ = m & 1023;
                float vx = acc[mt][nt][rr * 2];
                float vy = acc[mt][nt][rr * 2 + 1];
                if (mat == 2) {
                    size_t tb = ((size_t)(b_ * NH + h_) * 16 + (s_ >> 6)) * 4096;
                    int t_ = s_ & 63;
                    g_v[tb + (size_t)d_ * 64 + t_] = tf32_rna(vx);
                    g_v[tb + (size_t)(d_ + 1) * 64 + t_] = tf32_rna(vy);
                } else {
                    // Q/K: pair p = (2p, 2p+1); p = d_/2
                    size_t bhs = ((size_t)(b_ * NH + h_) * SEQ + s_);
                    uint2 pk = bf16_split_pack(vx * qscale, vy * qscale);
                    int p = d_ >> 1;
                    int b8 = p >> 3, pb = p & 7;
                    uint32_t* dst = (mat == 0) ? g_qu : g_ku;
                    *(uint2*)&dst[bhs * 64 + b8 * 16 + uslot(pb)] = pk;
                }
            }
        }
    }
}

// ---------------------------------------------------------------------------
// Kernel 3: output projection.
// ---------------------------------------------------------------------------
__global__ __launch_bounds__(256)
void proj_mma(const float* __restrict__ bias, float* __restrict__ out) {
    extern __shared__ char sm[];
    uint32_t base = smem_u32(sm);
    const int tid = threadIdx.x;
    const int wid = tid >> 5, lane = tid & 31;
    const int wm = wid & 1, wn = wid >> 1;
    const int r4 = lane >> 2, c4 = lane & 3;
    const int n0 = blockIdx.x * 128;
    const int m0 = blockIdx.y * 128;

    float acc[4][4][4] = {};
    gemm_mainloop(sm, base, g_att, g_wpr, m0, n0, acc);

#pragma unroll
    for (int mt = 0; mt < 4; ++mt) {
#pragma unroll
        for (int nt = 0; nt < 4; ++nt) {
            int n = n0 + wn * 32 + nt * 8 + c4 * 2;
            float2 bv = *(const float2*)&bias[n];
#pragma unroll
            for (int rr = 0; rr < 2; ++rr) {
                int m = m0 + wm * 64 + mt * 16 + r4 + rr * 8;
                float2 v = make_float2(acc[mt][nt][rr * 2] + bv.x,
                                       acc[mt][nt][rr * 2 + 1] + bv.y);
                *(float2*)&out[(size_t)m * EMB + n] = v;
            }
        }
    }
}

// ---------------------------------------------------------------------------
// Kernel 2: causal flash attention (R10 v5); epilogue writes bf16-packed g_att
// with pair j = (d, d+8) within 16-groups (thread-local values!).
// ---------------------------------------------------------------------------
#define QLU 80
#define VLD 72
#define ATTN_SMEM_BYTES ((128 * QLU + 3 * 64 * QLU) * 4 + 3 * 64 * VLD * 4)  // 157,696

__device__ __forceinline__ void attn_load_kv(uint32_t k_s, uint32_t v_s, int buf,
                                             const uint32_t* __restrict__ ksrc,
                                             const float* __restrict__ vsrc,
                                             int jt, int tid) {
    uint32_t kd = k_s + (uint32_t)buf * (64 * QLU * 4);
    uint32_t vd = v_s + (uint32_t)buf * (64 * VLD * 4);
    const uint32_t* kp = ksrc + (size_t)jt * 64 * 64;
    const float* vp = vsrc + (size_t)jt * 64 * 64;
#pragma unroll
    for (int i = 0; i < 4; ++i) {
        int idx = i * 256 + tid;
        int row = idx >> 4, c = idx & 15;
        CP_ASYNC16(kd + (row * QLU + c * 4) * 4, kp + row * 64 + c * 4);
    }
#pragma unroll
    for (int i = 0; i < 4; ++i) {
        int idx = i * 256 + tid;
        int row = idx >> 4, c = idx & 15;
        CP_ASYNC16(vd + (row * VLD + c * 4) * 4, vp + row * 64 + c * 4);
    }
    CP_COMMIT();
}

__global__ __launch_bounds__(256)
void attn_mma() {
    extern __shared__ uint32_t su[];
    uint32_t* Qi = su;
    uint32_t* Kb = Qi + 128 * QLU;
    float* Vbf = (float*)(Kb + 3 * 64 * QLU);

    const int tid = threadIdx.x;
    const int w = tid >> 5, lane = tid & 31;
    const int r4 = lane >> 2, c4 = lane & 3;
    const int qt = 7 - blockIdx.x;
    const int bh = blockIdx.y;

    const uint32_t* qsrc = g_qu + ((size_t)bh * SEQ + (size_t)qt * 128) * 64;
    const uint32_t* ksrc = g_ku + (size_t)bh * SEQ * 64;
    const float* vsrc = g_v + (size_t)bh * SEQ * HS;

    uint32_t q_s = smem_u32(Qi);
    uint32_t k_s = smem_u32(Kb);
    uint32_t v_s = smem_u32(Vbf);

#pragma unroll
    for (int i = 0; i < 8; ++i) {
        int idx = i * 256 + tid;
        int row = idx >> 4, c = idx & 15;
        CP_ASYNC16(q_s + (row * QLU + c * 4) * 4, qsrc + row * 64 + c * 4);
    }
    CP_COMMIT();

    const int jmax = 2 * qt + 1;
    attn_load_kv(k_s, v_s, 0, ksrc, vsrc, 0, tid);
    attn_load_kv(k_s, v_s, 1, ksrc, vsrc, 1, tid);

    float m0 = -1e30f, m1 = -1e30f, l0 = 0.0f, l1 = 0.0f;
    float ot[4][2][4] = {};

    for (int jt = 0; jt <= jmax; ++jt) {
        if (jt + 1 <= jmax) { CP_WAIT(1); } else { CP_WAIT(0); }
        __syncthreads();
        if (jt + 2 <= jmax)
            attn_load_kv(k_s, v_s, (jt + 2) % 3, ksrc, vsrc, jt + 2, tid);

        const int buf = jt % 3;
        const uint32_t* Ki = Kb + buf * 64 * QLU;
        const float* Vs = Vbf + buf * 64 * VLD;

        const bool active = (jt * 64 <= qt * 128 + w * 16 + 15);
        if (active) {
            float sacc[8][4] = {};
#pragma unroll
            for (int kb = 0; kb < 4; ++kb) {
                int ra = (w * 16 + r4) * QLU + kb * 16 + c4 * 4;
                uint4 q0 = *(const uint4*)&Qi[ra];
                uint4 q1 = *(const uint4*)&Qi[ra + 8 * QLU];
                uint32_t Ah[4] = {q0.x, q1.x, q0.z, q1.z};
                uint32_t Al[4] = {q0.y, q1.y, q0.w, q1.w};
#pragma unroll
                for (int nt = 0; nt < 8; ++nt) {
                    uint4 kv = *(const uint4*)&Ki[(nt * 8 + r4) * QLU + kb * 16 + c4 * 4];
                    uint32_t Bh[2] = {kv.x, kv.z};
                    uint32_t Bl[2] = {kv.y, kv.w};
                    mma_bf16(sacc[nt], Ah, Bh);
                    mma_bf16(sacc[nt], Ah, Bl);
                    mma_bf16(sacc[nt], Al, Bh);
                }
            }

            if (jt >= 2 * qt) {
                int rg0 = qt * 128 + w * 16 + r4;
#pragma unroll
                for (int nt = 0; nt < 8; ++nt) {
                    int cg = jt * 64 + nt * 8 + c4 * 2;
                    if (cg > rg0)         sacc[nt][0] = -1e30f;
                    if (cg + 1 > rg0)     sacc[nt][1] = -1e30f;
                    if (cg > rg0 + 8)     sacc[nt][2] = -1e30f;
                    if (cg + 1 > rg0 + 8) sacc[nt][3] = -1e30f;
                }
            }

            float mx0 = m0, mx1 = m1;
#pragma unroll
            for (int nt = 0; nt < 8; ++nt) {
                mx0 = fmaxf(mx0, fmaxf(sacc[nt][0], sacc[nt][1]));
                mx1 = fmaxf(mx1, fmaxf(sacc[nt][2], sacc[nt][3]));
            }
            mx0 = fmaxf(mx0, __shfl_xor_sync(0xFFFFFFFFu, mx0, 1));
            mx0 = fmaxf(mx0, __shfl_xor_sync(0xFFFFFFFFu, mx0, 2));
            mx1 = fmaxf(mx1, __shfl_xor_sync(0xFFFFFFFFu, mx1, 1));
            mx1 = fmaxf(mx1, __shfl_xor_sync(0xFFFFFFFFu, mx1, 2));
            float a0 = __expf(m0 - mx0);
            float a1 = __expf(m1 - mx1);
            m0 = mx0; m1 = mx1;

            float s0 = 0.0f, s1 = 0.0f;
#pragma unroll
            for (int nt = 0; nt < 8; ++nt) {
                float p00 = tf32_rna(__expf(sacc[nt][0] - mx0));
                float p01 = tf32_rna(__expf(sacc[nt][1] - mx0));
                float p10 = tf32_rna(__expf(sacc[nt][2] - mx1));
                float p11 = tf32_rna(__expf(sacc[nt][3] - mx1));
                s0 += p00 + p01;
                s1 += p10 + p11;
                sacc[nt][0] = p00; sacc[nt][1] = p01;
                sacc[nt][2] = p10; sacc[nt][3] = p11;
            }
            s0 += __shfl_xor_sync(0xFFFFFFFFu, s0, 1);
            s0 += __shfl_xor_sync(0xFFFFFFFFu, s0, 2);
            s1 += __shfl_xor_sync(0xFFFFFFFFu, s1, 1);
            s1 += __shfl_xor_sync(0xFFFFFFFFu, s1, 2);
            l0 = l0 * a0 + s0;
            l1 = l1 * a1 + s1;

            float aq00 = __shfl_sync(0xFFFFFFFFu, a0, (2 * c4) * 4);
            float aq01 = __shfl_sync(0xFFFFFFFFu, a0, (2 * c4 + 1) * 4);
            float aq10 = __shfl_sync(0xFFFFFFFFu, a1, (2 * c4) * 4);
            float aq11 = __shfl_sync(0xFFFFFFFFu, a1, (2 * c4 + 1) * 4);
#pragma unroll
            for (int db = 0; db < 4; ++db) {
                ot[db][0][0] *= aq00; ot[db][0][1] *= aq01;
                ot[db][0][2] *= aq00; ot[db][0][3] *= aq01;
                ot[db][1][0] *= aq10; ot[db][1][1] *= aq11;
                ot[db][1][2] *= aq10; ot[db][1][3] *= aq11;
            }

#pragma unroll
            for (int g = 0; g < 8; ++g) {
                uint32_t bf0[2] = {__float_as_uint(sacc[g][0]), __float_as_uint(sacc[g][1])};
                uint32_t bf1[2] = {__float_as_uint(sacc[g][2]), __float_as_uint(sacc[g][3])};
#pragma unroll
                for (int db = 0; db < 4; ++db) {
                    int ra = (db * 16 + r4) * VLD + g * 8 + 2 * c4;
                    float2 u = *(const float2*)&Vs[ra];
                    float2 w2 = *(const float2*)&Vs[ra + 8 * VLD];
                    uint32_t af[4] = {__float_as_uint(u.x), __float_as_uint(w2.x),
                                      __float_as_uint(u.y), __float_as_uint(w2.y)};
                    mma_tf32(ot[db][0], af, bf0);
                    mma_tf32(ot[db][1], af, bf1);
                }
            }
        }
    }

    // Epilogue: O = (O^T)^T / l, bf16-pack pairs (d, d+8), write g_att.
    const int b_ = bh >> 4, h_ = bh & 15;
    float lq00 = __shfl_sync(0xFFFFFFFFu, l0, (2 * c4) * 4);
    float lq01 = __shfl_sync(0xFFFFFFFFu, l0, (2 * c4 + 1) * 4);
    float lq10 = __shfl_sync(0xFFFFFFFFu, l1, (2 * c4) * 4);
    float lq11 = __shfl_sync(0xFFFFFFFFu, l1, (2 * c4 + 1) * 4);
    float iv[2][2] = {{1.0f / lq00, 1.0f / lq01}, {1.0f / lq10, 1.0f / lq11}};
    const int us = uslot(r4);
#pragma unroll
    for (int db = 0; db < 4; ++db) {
        int blk = (h_ * 4 + db) * 16 + us;   // u32 offset within packed row
#pragma unroll
        for (int qh = 0; qh < 2; ++qh) {
            int q0 = qt * 128 + w * 16 + qh * 8 + 2 * c4;
            size_t row0 = ((size_t)b_ * SEQ + q0) * (size_t)EMB;
            size_t row1 = ((size_t)b_ * SEQ + q0 + 1) * (size_t)EMB;
            uint2 pk0 = bf16_split_pack(ot[db][qh][0] * iv[qh][0],
                                        ot[db][qh][2] * iv[qh][0]);
            uint2 pk1 = bf16_split_pack(ot[db][qh][1] * iv[qh][1],
                                        ot[db][qh][3] * iv[qh][1]);
            *(uint2*)&g_att[row0 + blk] = pk0;
            *(uint2*)&g_att[row1 + blk] = pk1;
        }
    }
}

// ---------------------------------------------------------------------------
extern "C" void kernel_launch(void* const* d_in, const int* in_sizes, int n_in,
                              void* d_out, int out_size) {
    (void)in_sizes; (void)n_in; (void)out_size;
    const float* x     = (const float*)d_in[0];
    const float* Wq    = (const float*)d_in[1];
    const float* Wk    = (const float*)d_in[2];
    const float* Wv    = (const float*)d_in[3];
    const float* Wproj = (const float*)d_in[4];
    const float* bproj = (const float*)d_in[5];
    float* out = (float*)d_out;

    cudaFuncSetAttribute(qkv_mma, cudaFuncAttributeMaxDynamicSharedMemorySize, MMA_SMEM_BYTES);
    cudaFuncSetAttribute(proj_mma, cudaFuncAttributeMaxDynamicSharedMemorySize, MMA_SMEM_BYTES);
    cudaFuncSetAttribute(attn_mma, cudaFuncAttributeMaxDynamicSharedMemorySize, ATTN_SMEM_BYTES);

    uint32_t* p_xr = nullptr;  cudaGetSymbolAddress((void**)&p_xr, g_xr);
    uint32_t* p_wpr = nullptr; cudaGetSymbolAddress((void**)&p_wpr, g_wpr);

    round_pack_kernel<<<M_TOT * EMB / 16 / 256, 256>>>(x, p_xr);
    round_pack_kernel<<<EMB * EMB / 16 / 256, 256>>>(Wproj, p_wpr);
    wt_transpose<<<dim3(16, 16, 3), 256>>>(Wq, Wk, Wv);
    qkv_mma<<<dim3(24, 64), 256, MMA_SMEM_BYTES>>>();
    attn_mma<<<dim3(8, Bsz * NH), 256, ATTN_SMEM_BYTES>>>();
    proj_mma<<<dim3(8, 64), 256, MMA_SMEM_BYTES>>>(bproj, out);
}

// round 13
// speedup vs baseline: 1.1898x; 1.1898x over previous
#include <cuda_runtime.h>
#include <cuda_bf16.h>
#include <math.h>
#include <stdint.h>

// Problem constants
#define Bsz 8
#define SEQ 1024
#define EMB 1024
#define NH  16
#define HS  64
#define M_TOT (Bsz * SEQ)   // 8192

// Scratch layouts (R10):
//  g_qu, g_ku : [BH][S][64 uint32] bf16 hi/lo pair-packed rows (Q pre-scaled)
//  g_v       : [BH][tile jt][d][t]  V transposed per 64-token tile, tf32-rna'd
//  g_att     : [B,S,H*HS] cols perm8'd within 8-groups (proj A-frags)
//  g_xr/g_wt/g_wpr : perm8'd tf32 GEMM operands
__device__ uint32_t g_qu[Bsz * NH * SEQ * 64];
__device__ uint32_t g_ku[Bsz * NH * SEQ * 64];
__device__ float g_v[Bsz * NH * SEQ * HS];
__device__ float g_att[M_TOT * EMB];
__device__ float g_wt[3 * EMB * EMB];
__device__ float g_xr[M_TOT * EMB];
__device__ float g_wpr[EMB * EMB];

// ---------------------------------------------------------------------------
// Helpers
// ---------------------------------------------------------------------------
__device__ __forceinline__ uint32_t smem_u32(const void* p) {
    uint32_t a;
    asm("{ .reg .u64 t; cvta.to.shared.u64 t, %1; cvt.u32.u64 %0, t; }" : "=r"(a) : "l"(p));
    return a;
}
__device__ __forceinline__ float tf32_rna(float x) {
    uint32_t u;
    asm("cvt.rna.tf32.f32 %0, %1;" : "=r"(u) : "f"(x));
    return __uint_as_float(u);
}
__device__ __forceinline__ int perm8(int t) {   // pair-permute within 8-group
    int r = t & 7;
    return (t & ~7) + ((r & 4) ? 2 * (r & 3) + 1 : 2 * r);
}
// Split (x,y) into bf16 hi/lo pairs: {hi_pack, lo_pack}, low half = x.
__device__ __forceinline__ uint2 bf16_split_pack(float x, float y) {
    __nv_bfloat16 hx = __float2bfloat16(x);
    __nv_bfloat16 hy = __float2bfloat16(y);
    float lx = x - __bfloat162float(hx);
    float ly = y - __bfloat162float(hy);
    __nv_bfloat162 hp = __halves2bfloat162(hx, hy);
    __nv_bfloat162 lp = __halves2bfloat162(__float2bfloat16(lx), __float2bfloat16(ly));
    uint2 r;
    r.x = *(uint32_t*)&hp;
    r.y = *(uint32_t*)&lp;
    return r;
}
#define CP_ASYNC16(dst, src) \
    asm volatile("cp.async.cg.shared.global [%0], [%1], 16;" :: "r"(dst), "l"(src))
#define CP_COMMIT() asm volatile("cp.async.commit_group;" ::: "memory")
#define CP_WAIT(n)  asm volatile("cp.async.wait_group %0;" :: "n"(n) : "memory")

__device__ __forceinline__ void mma_tf32(float* d, const uint32_t* a, const uint32_t* b) {
    asm volatile(
        "mma.sync.aligned.m16n8k8.row.col.f32.tf32.tf32.f32 "
        "{%0,%1,%2,%3}, {%4,%5,%6,%7}, {%8,%9}, {%0,%1,%2,%3};"
        : "+f"(d[0]), "+f"(d[1]), "+f"(d[2]), "+f"(d[3])
        : "r"(a[0]), "r"(a[1]), "r"(a[2]), "r"(a[3]), "r"(b[0]), "r"(b[1]));
}
__device__ __forceinline__ void mma_bf16(float* d, const uint32_t* a, const uint32_t* b) {
    asm volatile(
        "mma.sync.aligned.m16n8k16.row.col.f32.bf16.bf16.f32 "
        "{%0,%1,%2,%3}, {%4,%5,%6,%7}, {%8,%9}, {%0,%1,%2,%3};"
        : "+f"(d[0]), "+f"(d[1]), "+f"(d[2]), "+f"(d[3])
        : "r"(a[0]), "r"(a[1]), "r"(a[2]), "r"(a[3]), "r"(b[0]), "r"(b[1]));
}

// ---------------------------------------------------------------------------
// Prep kernels (R10)
// ---------------------------------------------------------------------------
__global__ __launch_bounds__(256)
void round_perm_kernel(const float* __restrict__ in, float* __restrict__ out) {
    size_t g = (size_t)blockIdx.x * 256 + threadIdx.x;
    size_t base = g * 8;
    float4 a = *(const float4*)&in[base];
    float4 b = *(const float4*)&in[base + 4];
    float4 o0 = make_float4(tf32_rna(a.x), tf32_rna(b.x), tf32_rna(a.y), tf32_rna(b.y));
    float4 o1 = make_float4(tf32_rna(a.z), tf32_rna(b.z), tf32_rna(a.w), tf32_rna(b.w));
    *(float4*)&out[base] = o0;
    *(float4*)&out[base + 4] = o1;
}

__global__ __launch_bounds__(256)
void wt_transpose(const float* __restrict__ Wq,
                  const float* __restrict__ Wk,
                  const float* __restrict__ Wv) {
    __shared__ float t[64][65];
    const int tid = threadIdx.x;
    const int et = blockIdx.x;
    const int h  = blockIdx.y;
    const int mat = blockIdx.z;
    const float* W = (mat == 0) ? Wq : (mat == 1) ? Wk : Wv;
    const float* src = W + (size_t)h * (EMB * HS) + (size_t)(et * 64) * HS;
    float* out = g_wt + (size_t)mat * (EMB * EMB);

    for (int i = tid; i < 64 * 64; i += 256) {
        int e = i >> 6, d = i & 63;
        t[e][d] = src[(size_t)e * HS + d];
    }
    __syncthreads();
    for (int i = tid; i < 64 * 64; i += 256) {
        int d = i >> 6, e = i & 63;
        out[(size_t)(h * 64 + d) * EMB + et * 64 + perm8(e)] = tf32_rna(t[e][d]);
    }
}

// ---------------------------------------------------------------------------
// tf32 mma.sync GEMM core: C[128,128] = A @ B^T
// R10 fragment path (perm8 + float2 LDS, LDF 40); NEW: 3-stage ring,
// single __syncthreads per chunk.
// ---------------------------------------------------------------------------
#define LDF 40
#define TILE_F (128 * LDF)
#define BUF_BYTES (2 * TILE_F * 4)          // A+B one stage = 40960
#define MMA_SMEM_BYTES (3 * BUF_BYTES)      // 122880 -> 1 CTA/SM
#define NCHUNK (EMB / 32)

__device__ __forceinline__ void gemm_load_chunk(uint32_t base, int buf, int kc,
                                                const float* __restrict__ Ag,
                                                const float* __restrict__ Bg,
                                                int m0, int n0, int tid) {
    uint32_t a_s = base + (uint32_t)buf * BUF_BYTES;
    uint32_t b_s = a_s + TILE_F * 4;
    const float* ap = Ag + (size_t)m0 * EMB + kc * 32;
    const float* bp = Bg + (size_t)n0 * EMB + kc * 32;
#pragma unroll
    for (int i = 0; i < 4; ++i) {
        int idx = i * 256 + tid;
        int row = idx >> 3, c = idx & 7;
        CP_ASYNC16(a_s + row * (LDF * 4) + c * 16, ap + (size_t)row * EMB + c * 4);
    }
#pragma unroll
    for (int i = 0; i < 4; ++i) {
        int idx = i * 256 + tid;
        int row = idx >> 3, c = idx & 7;
        CP_ASYNC16(b_s + row * (LDF * 4) + c * 16, bp + (size_t)row * EMB + c * 4);
    }
    CP_COMMIT();
}

__device__ __forceinline__ void gemm_mainloop(char* smraw, uint32_t base,
                                              const float* __restrict__ Ag,
                                              const float* __restrict__ Bg,
                                              int m0, int n0,
                                              float acc[4][4][4]) {
    const int tid = threadIdx.x;
    const int wid = tid >> 5, lane = tid & 31;
    const int wm = wid & 1, wn = wid >> 1;
    const int r4 = lane >> 2, c4 = lane & 3;

    gemm_load_chunk(base, 0, 0, Ag, Bg, m0, n0, tid);
    gemm_load_chunk(base, 1, 1, Ag, Bg, m0, n0, tid);

    for (int kc = 0; kc < NCHUNK; ++kc) {
        if (kc + 1 < NCHUNK) { CP_WAIT(1); } else { CP_WAIT(0); }
        __syncthreads();
        // Buffer (kc+2)%3 == (kc-1)%3 was fully consumed before this barrier.
        if (kc + 2 < NCHUNK)
            gemm_load_chunk(base, (kc + 2) % 3, kc + 2, Ag, Bg, m0, n0, tid);

        const float* As = (const float*)(smraw + (size_t)(kc % 3) * BUF_BYTES);
        const float* Bs = As + TILE_F;

#pragma unroll
        for (int ks = 0; ks < 4; ++ks) {
            const int k0 = ks * 8;
            uint32_t af[4][4], bf[4][2];
#pragma unroll
            for (int mt = 0; mt < 4; ++mt) {
                int rb = (wm * 64 + mt * 16 + r4) * LDF + k0 + 2 * c4;
                float2 u = *(const float2*)&As[rb];
                float2 w = *(const float2*)&As[rb + 8 * LDF];
                af[mt][0] = __float_as_uint(u.x);
                af[mt][1] = __float_as_uint(w.x);
                af[mt][2] = __float_as_uint(u.y);
                af[mt][3] = __float_as_uint(w.y);
            }
#pragma unroll
            for (int nt = 0; nt < 4; ++nt) {
                int nb = (wn * 32 + nt * 8 + r4) * LDF + k0 + 2 * c4;
                float2 u = *(const float2*)&Bs[nb];
                bf[nt][0] = __float_as_uint(u.x);
                bf[nt][1] = __float_as_uint(u.y);
            }
#pragma unroll
            for (int mt = 0; mt < 4; ++mt)
#pragma unroll
                for (int nt = 0; nt < 4; ++nt)
                    mma_tf32(acc[mt][nt], af[mt], bf[nt]);
        }
    }
}

// ---------------------------------------------------------------------------
// Kernel 1: QKV projection (R10 epilogue: bf16-packed Q/K, tf32 V^T tiles).
// ---------------------------------------------------------------------------
__global__ __launch_bounds__(256)
void qkv_mma(void) {
    extern __shared__ char sm[];
    uint32_t base = smem_u32(sm);
    const int tid = threadIdx.x;
    const int wid = tid >> 5, lane = tid & 31;
    const int wm = wid & 1, wn = wid >> 1;
    const int r4 = lane >> 2, c4 = lane & 3;
    const int mat = blockIdx.x >> 3;
    const int n0 = (blockIdx.x & 7) * 128;
    const int m0 = blockIdx.y * 128;
    const float* Bg = g_wt + (size_t)mat * (EMB * EMB);

    float acc[4][4][4] = {};
    gemm_mainloop(sm, base, g_xr, Bg, m0, n0, acc);

    const float qscale = (mat == 0) ? 0.125f : 1.0f;
#pragma unroll
    for (int mt = 0; mt < 4; ++mt) {
#pragma unroll
        for (int nt = 0; nt < 4; ++nt) {
            int n = n0 + wn * 32 + nt * 8 + c4 * 2;
            int h_ = n >> 6, d_ = n & 63;
#pragma unroll
            for (int rr = 0; rr < 2; ++rr) {
                int m = m0 + wm * 64 + mt * 16 + r4 + rr * 8;
                int b_ = m >> 10, s_ = m & 1023;
                float vx = acc[mt][nt][rr * 2];
                float vy = acc[mt][nt][rr * 2 + 1];
                if (mat == 2) {
                    // V: [bh][tile][d][t]  tf32, plain transpose
                    size_t tb = ((size_t)(b_ * NH + h_) * 16 + (s_ >> 6)) * 4096;
                    int t_ = s_ & 63;
                    g_v[tb + (size_t)d_ * 64 + t_] = tf32_rna(vx);
                    g_v[tb + (size_t)(d_ + 1) * 64 + t_] = tf32_rna(vy);
                } else {
                    // Q/K: bf16 hi/lo pair-packed row of 64 uint32
                    size_t bhs = ((size_t)(b_ * NH + h_) * SEQ + s_);
                    uint2 pk = bf16_split_pack(vx * qscale, vy * qscale);
                    int p = d_ >> 1;
                    int b8 = p >> 3, pb = p & 7;
                    int u = b8 * 16 + (pb & 3) * 4 + ((pb >> 2) << 1);
                    uint32_t* dst = (mat == 0) ? g_qu : g_ku;
                    *(uint2*)&dst[bhs * 64 + u] = pk;
                }
            }
        }
    }
}

// ---------------------------------------------------------------------------
// Kernel 3: output projection.
// ---------------------------------------------------------------------------
__global__ __launch_bounds__(256)
void proj_mma(const float* __restrict__ bias, float* __restrict__ out) {
    extern __shared__ char sm[];
    uint32_t base = smem_u32(sm);
    const int tid = threadIdx.x;
    const int wid = tid >> 5, lane = tid & 31;
    const int wm = wid & 1, wn = wid >> 1;
    const int r4 = lane >> 2, c4 = lane & 3;
    const int n0 = blockIdx.x * 128;
    const int m0 = blockIdx.y * 128;

    float acc[4][4][4] = {};
    gemm_mainloop(sm, base, g_att, g_wpr, m0, n0, acc);

#pragma unroll
    for (int mt = 0; mt < 4; ++mt) {
#pragma unroll
        for (int nt = 0; nt < 4; ++nt) {
            int n = n0 + wn * 32 + nt * 8 + c4 * 2;
            float2 bv = *(const float2*)&bias[n];
#pragma unroll
            for (int rr = 0; rr < 2; ++rr) {
                int m = m0 + wm * 64 + mt * 16 + r4 + rr * 8;
                float2 v = make_float2(acc[mt][nt][rr * 2] + bv.x,
                                       acc[mt][nt][rr * 2 + 1] + bv.y);
                *(float2*)&out[(size_t)m * EMB + n] = v;
            }
        }
    }
}

// ---------------------------------------------------------------------------
// Kernel 2: causal flash attention (R10 v5, unchanged).
// ---------------------------------------------------------------------------
#define QLU 80
#define VLD 72
#define ATTN_SMEM_BYTES ((128 * QLU + 3 * 64 * QLU) * 4 + 3 * 64 * VLD * 4)  // 157,696

__device__ __forceinline__ void attn_load_kv(uint32_t k_s, uint32_t v_s, int buf,
                                             const uint32_t* __restrict__ ksrc,
                                             const float* __restrict__ vsrc,
                                             int jt, int tid) {
    uint32_t kd = k_s + (uint32_t)buf * (64 * QLU * 4);
    uint32_t vd = v_s + (uint32_t)buf * (64 * VLD * 4);
    const uint32_t* kp = ksrc + (size_t)jt * 64 * 64;
    const float* vp = vsrc + (size_t)jt * 64 * 64;
#pragma unroll
    for (int i = 0; i < 4; ++i) {
        int idx = i * 256 + tid;
        int row = idx >> 4, c = idx & 15;
        CP_ASYNC16(kd + (row * QLU + c * 4) * 4, kp + row * 64 + c * 4);
    }
#pragma unroll
    for (int i = 0; i < 4; ++i) {
        int idx = i * 256 + tid;
        int row = idx >> 4, c = idx & 15;
        CP_ASYNC16(vd + (row * VLD + c * 4) * 4, vp + row * 64 + c * 4);
    }
    CP_COMMIT();
}

__global__ __launch_bounds__(256)
void attn_mma() {
    extern __shared__ uint32_t su[];
    uint32_t* Qi = su;
    uint32_t* Kb = Qi + 128 * QLU;
    float* Vbf = (float*)(Kb + 3 * 64 * QLU);

    const int tid = threadIdx.x;
    const int w = tid >> 5, lane = tid & 31;
    const int r4 = lane >> 2, c4 = lane & 3;
    const int qt = 7 - blockIdx.x;
    const int bh = blockIdx.y;

    const uint32_t* qsrc = g_qu + ((size_t)bh * SEQ + (size_t)qt * 128) * 64;
    const uint32_t* ksrc = g_ku + (size_t)bh * SEQ * 64;
    const float* vsrc = g_v + (size_t)bh * SEQ * HS;

    uint32_t q_s = smem_u32(Qi);
    uint32_t k_s = smem_u32(Kb);
    uint32_t v_s = smem_u32(Vbf);

#pragma unroll
    for (int i = 0; i < 8; ++i) {
        int idx = i * 256 + tid;
        int row = idx >> 4, c = idx & 15;
        CP_ASYNC16(q_s + (row * QLU + c * 4) * 4, qsrc + row * 64 + c * 4);
    }
    CP_COMMIT();

    const int jmax = 2 * qt + 1;
    attn_load_kv(k_s, v_s, 0, ksrc, vsrc, 0, tid);
    attn_load_kv(k_s, v_s, 1, ksrc, vsrc, 1, tid);

    float m0 = -1e30f, m1 = -1e30f, l0 = 0.0f, l1 = 0.0f;
    float ot[4][2][4] = {};

    for (int jt = 0; jt <= jmax; ++jt) {
        if (jt + 1 <= jmax) { CP_WAIT(1); } else { CP_WAIT(0); }
        __syncthreads();
        if (jt + 2 <= jmax)
            attn_load_kv(k_s, v_s, (jt + 2) % 3, ksrc, vsrc, jt + 2, tid);

        const int buf = jt % 3;
        const uint32_t* Ki = Kb + buf * 64 * QLU;
        const float* Vs = Vbf + buf * 64 * VLD;

        const bool active = (jt * 64 <= qt * 128 + w * 16 + 15);
        if (active) {
            float sacc[8][4] = {};
#pragma unroll
            for (int kb = 0; kb < 4; ++kb) {
                int ra = (w * 16 + r4) * QLU + kb * 16 + c4 * 4;
                uint4 q0 = *(const uint4*)&Qi[ra];
                uint4 q1 = *(const uint4*)&Qi[ra + 8 * QLU];
                uint32_t Ah[4] = {q0.x, q1.x, q0.z, q1.z};
                uint32_t Al[4] = {q0.y, q1.y, q0.w, q1.w};
#pragma unroll
                for (int nt = 0; nt < 8; ++nt) {
                    uint4 kv = *(const uint4*)&Ki[(nt * 8 + r4) * QLU + kb * 16 + c4 * 4];
                    uint32_t Bh[2] = {kv.x, kv.z};
                    uint32_t Bl[2] = {kv.y, kv.w};
                    mma_bf16(sacc[nt], Ah, Bh);
                    mma_bf16(sacc[nt], Ah, Bl);
                    mma_bf16(sacc[nt], Al, Bh);
                }
            }

            if (jt >= 2 * qt) {
                int rg0 = qt * 128 + w * 16 + r4;
#pragma unroll
                for (int nt = 0; nt < 8; ++nt) {
                    int cg = jt * 64 + nt * 8 + c4 * 2;
                    if (cg > rg0)         sacc[nt][0] = -1e30f;
                    if (cg + 1 > rg0)     sacc[nt][1] = -1e30f;
                    if (cg > rg0 + 8)     sacc[nt][2] = -1e30f;
                    if (cg + 1 > rg0 + 8) sacc[nt][3] = -1e30f;
                }
            }

            float mx0 = m0, mx1 = m1;
#pragma unroll
            for (int nt = 0; nt < 8; ++nt) {
                mx0 = fmaxf(mx0, fmaxf(sacc[nt][0], sacc[nt][1]));
                mx1 = fmaxf(mx1, fmaxf(sacc[nt][2], sacc[nt][3]));
            }
            mx0 = fmaxf(mx0, __shfl_xor_sync(0xFFFFFFFFu, mx0, 1));
            mx0 = fmaxf(mx0, __shfl_xor_sync(0xFFFFFFFFu, mx0, 2));
            mx1 = fmaxf(mx1, __shfl_xor_sync(0xFFFFFFFFu, mx1, 1));
            mx1 = fmaxf(mx1, __shfl_xor_sync(0xFFFFFFFFu, mx1, 2));
            float a0 = __expf(m0 - mx0);
            float a1 = __expf(m1 - mx1);
            m0 = mx0; m1 = mx1;

            float s0 = 0.0f, s1 = 0.0f;
#pragma unroll
            for (int nt = 0; nt < 8; ++nt) {
                float p00 = tf32_rna(__expf(sacc[nt][0] - mx0));
                float p01 = tf32_rna(__expf(sacc[nt][1] - mx0));
                float p10 = tf32_rna(__expf(sacc[nt][2] - mx1));
                float p11 = tf32_rna(__expf(sacc[nt][3] - mx1));
                s0 += p00 + p01;
                s1 += p10 + p11;
                sacc[nt][0] = p00; sacc[nt][1] = p01;
                sacc[nt][2] = p10; sacc[nt][3] = p11;
            }
            s0 += __shfl_xor_sync(0xFFFFFFFFu, s0, 1);
            s0 += __shfl_xor_sync(0xFFFFFFFFu, s0, 2);
            s1 += __shfl_xor_sync(0xFFFFFFFFu, s1, 1);
            s1 += __shfl_xor_sync(0xFFFFFFFFu, s1, 2);
            l0 = l0 * a0 + s0;
            l1 = l1 * a1 + s1;

            float aq00 = __shfl_sync(0xFFFFFFFFu, a0, (2 * c4) * 4);
            float aq01 = __shfl_sync(0xFFFFFFFFu, a0, (2 * c4 + 1) * 4);
            float aq10 = __shfl_sync(0xFFFFFFFFu, a1, (2 * c4) * 4);
            float aq11 = __shfl_sync(0xFFFFFFFFu, a1, (2 * c4 + 1) * 4);
#pragma unroll
            for (int db = 0; db < 4; ++db) {
                ot[db][0][0] *= aq00; ot[db][0][1] *= aq01;
                ot[db][0][2] *= aq00; ot[db][0][3] *= aq01;
                ot[db][1][0] *= aq10; ot[db][1][1] *= aq11;
                ot[db][1][2] *= aq10; ot[db][1][3] *= aq11;
            }

#pragma unroll
            for (int g = 0; g < 8; ++g) {
                uint32_t bf0[2] = {__float_as_uint(sacc[g][0]), __float_as_uint(sacc[g][1])};
                uint32_t bf1[2] = {__float_as_uint(sacc[g][2]), __float_as_uint(sacc[g][3])};
#pragma unroll
                for (int db = 0; db < 4; ++db) {
                    int ra = (db * 16 + r4) * VLD + g * 8 + 2 * c4;
                    float2 u = *(const float2*)&Vs[ra];
                    float2 w2 = *(const float2*)&Vs[ra + 8 * VLD];
                    uint32_t af[4] = {__float_as_uint(u.x), __float_as_uint(w2.x),
                                      __float_as_uint(u.y), __float_as_uint(w2.y)};
                    mma_tf32(ot[db][0], af, bf0);
                    mma_tf32(ot[db][1], af, bf1);
                }
            }
        }
    }

    // Epilogue: O = (O^T)^T / l, tf32-round, write g_att (cols perm8'd).
    const int b_ = bh >> 4, h_ = bh & 15;
    float lq00 = __shfl_sync(0xFFFFFFFFu, l0, (2 * c4) * 4);
    float lq01 = __shfl_sync(0xFFFFFFFFu, l0, (2 * c4 + 1) * 4);
    float lq10 = __shfl_sync(0xFFFFFFFFu, l1, (2 * c4) * 4);
    float lq11 = __shfl_sync(0xFFFFFFFFu, l1, (2 * c4 + 1) * 4);
    float iv[2][2] = {{1.0f / lq00, 1.0f / lq01}, {1.0f / lq10, 1.0f / lq11}};
    const int doff = (r4 & 4) ? 2 * (r4 & 3) + 1 : 2 * r4;
#pragma unroll
    for (int db = 0; db < 4; ++db) {
        int p0 = db * 16 + doff;
        int p8 = db * 16 + 8 + doff;
#pragma unroll
        for (int qh = 0; qh < 2; ++qh) {
            int q0 = qt * 128 + w * 16 + qh * 8 + 2 * c4;
            size_t row0 = (((size_t)b_ * SEQ + q0) * NH + h_) * (size_t)HS;
            size_t row1 = (((size_t)b_ * SEQ + q0 + 1) * NH + h_) * (size_t)HS;
            g_att[row0 + p0] = tf32_rna(ot[db][qh][0] * iv[qh][0]);
            g_att[row1 + p0] = tf32_rna(ot[db][qh][1] * iv[qh][1]);
            g_att[row0 + p8] = tf32_rna(ot[db][qh][2] * iv[qh][0]);
            g_att[row1 + p8] = tf32_rna(ot[db][qh][3] * iv[qh][1]);
        }
    }
}

// ---------------------------------------------------------------------------
extern "C" void kernel_launch(void* const* d_in, const int* in_sizes, int n_in,
                              void* d_out, int out_size) {
    (void)in_sizes; (void)n_in; (void)out_size;
    const float* x     = (const float*)d_in[0];
    const float* Wq    = (const float*)d_in[1];
    const float* Wk    = (const float*)d_in[2];
    const float* Wv    = (const float*)d_in[3];
    const float* Wproj = (const float*)d_in[4];
    const float* bproj = (const float*)d_in[5];
    float* out = (float*)d_out;

    cudaFuncSetAttribute(qkv_mma, cudaFuncAttributeMaxDynamicSharedMemorySize, MMA_SMEM_BYTES);
    cudaFuncSetAttribute(proj_mma, cudaFuncAttributeMaxDynamicSharedMemorySize, MMA_SMEM_BYTES);
    cudaFuncSetAttribute(attn_mma, cudaFuncAttributeMaxDynamicSharedMemorySize, ATTN_SMEM_BYTES);

    float* p_xr = nullptr;  cudaGetSymbolAddress((void**)&p_xr, g_xr);
    float* p_wpr = nullptr; cudaGetSymbolAddress((void**)&p_wpr, g_wpr);

    round_perm_kernel<<<M_TOT * EMB / 8 / 256, 256>>>(x, p_xr);
    round_perm_kernel<<<EMB * EMB / 8 / 256, 256>>>(Wproj, p_wpr);
    wt_transpose<<<dim3(16, 16, 3), 256>>>(Wq, Wk, Wv);
    qkv_mma<<<dim3(24, 64), 256, MMA_SMEM_BYTES>>>();
    attn_mma<<<dim3(8, Bsz * NH), 256, ATTN_SMEM_BYTES>>>();
    proj_mma<<<dim3(8, 64), 256, MMA_SMEM_BYTES>>>(bproj, out);
}

// round 15
// speedup vs baseline: 1.3717x; 1.1529x over previous
#include <cuda_runtime.h>
#include <cuda_bf16.h>
#include <math.h>
#include <stdint.h>

// Problem constants
#define Bsz 8
#define SEQ 1024
#define EMB 1024
#define NH  16
#define HS  64
#define M_TOT (Bsz * SEQ)   // 8192

// Scratch layouts (R10):
//  g_qu, g_ku : [BH][S][64 uint32] bf16 hi/lo pair-packed rows (Q pre-scaled)
//  g_v       : [BH][tile jt][d][t]  V transposed per 64-token tile, tf32-rna'd
//  g_att     : [B,S,H*HS] cols perm8'd within 8-groups (proj A-frags)
//  g_xr/g_wt/g_wpr : perm8'd tf32 GEMM operands
__device__ uint32_t g_qu[Bsz * NH * SEQ * 64];
__device__ uint32_t g_ku[Bsz * NH * SEQ * 64];
__device__ float g_v[Bsz * NH * SEQ * HS];
__device__ float g_att[M_TOT * EMB];
__device__ float g_wt[3 * EMB * EMB];
__device__ float g_xr[M_TOT * EMB];
__device__ float g_wpr[EMB * EMB];

// ---------------------------------------------------------------------------
// Helpers
// ---------------------------------------------------------------------------
__device__ __forceinline__ uint32_t smem_u32(const void* p) {
    uint32_t a;
    asm("{ .reg .u64 t; cvta.to.shared.u64 t, %1; cvt.u32.u64 %0, t; }" : "=r"(a) : "l"(p));
    return a;
}
__device__ __forceinline__ float tf32_rna(float x) {
    uint32_t u;
    asm("cvt.rna.tf32.f32 %0, %1;" : "=r"(u) : "f"(x));
    return __uint_as_float(u);
}
__device__ __forceinline__ int perm8(int t) {   // pair-permute within 8-group
    int r = t & 7;
    return (t & ~7) + ((r & 4) ? 2 * (r & 3) + 1 : 2 * r);
}
// Split (x,y) into bf16 hi/lo pairs: {hi_pack, lo_pack}, low half = x.
__device__ __forceinline__ uint2 bf16_split_pack(float x, float y) {
    __nv_bfloat16 hx = __float2bfloat16(x);
    __nv_bfloat16 hy = __float2bfloat16(y);
    float lx = x - __bfloat162float(hx);
    float ly = y - __bfloat162float(hy);
    __nv_bfloat162 hp = __halves2bfloat162(hx, hy);
    __nv_bfloat162 lp = __halves2bfloat162(__float2bfloat16(lx), __float2bfloat16(ly));
    uint2 r;
    r.x = *(uint32_t*)&hp;
    r.y = *(uint32_t*)&lp;
    return r;
}
#define CP_ASYNC16(dst, src) \
    asm volatile("cp.async.cg.shared.global [%0], [%1], 16;" :: "r"(dst), "l"(src))
#define CP_COMMIT() asm volatile("cp.async.commit_group;" ::: "memory")
#define CP_WAIT(n)  asm volatile("cp.async.wait_group %0;" :: "n"(n) : "memory")

__device__ __forceinline__ void mma_tf32(float* d, const uint32_t* a, const uint32_t* b) {
    asm volatile(
        "mma.sync.aligned.m16n8k8.row.col.f32.tf32.tf32.f32 "
        "{%0,%1,%2,%3}, {%4,%5,%6,%7}, {%8,%9}, {%0,%1,%2,%3};"
        : "+f"(d[0]), "+f"(d[1]), "+f"(d[2]), "+f"(d[3])
        : "r"(a[0]), "r"(a[1]), "r"(a[2]), "r"(a[3]), "r"(b[0]), "r"(b[1]));
}
__device__ __forceinline__ void mma_bf16(float* d, const uint32_t* a, const uint32_t* b) {
    asm volatile(
        "mma.sync.aligned.m16n8k16.row.col.f32.bf16.bf16.f32 "
        "{%0,%1,%2,%3}, {%4,%5,%6,%7}, {%8,%9}, {%0,%1,%2,%3};"
        : "+f"(d[0]), "+f"(d[1]), "+f"(d[2]), "+f"(d[3])
        : "r"(a[0]), "r"(a[1]), "r"(a[2]), "r"(a[3]), "r"(b[0]), "r"(b[1]));
}

// ---------------------------------------------------------------------------
// Prep kernels (R10)
// ---------------------------------------------------------------------------
__global__ __launch_bounds__(256)
void round_perm_kernel(const float* __restrict__ in, float* __restrict__ out) {
    size_t g = (size_t)blockIdx.x * 256 + threadIdx.x;
    size_t base = g * 8;
    float4 a = *(const float4*)&in[base];
    float4 b = *(const float4*)&in[base + 4];
    float4 o0 = make_float4(tf32_rna(a.x), tf32_rna(b.x), tf32_rna(a.y), tf32_rna(b.y));
    float4 o1 = make_float4(tf32_rna(a.z), tf32_rna(b.z), tf32_rna(a.w), tf32_rna(b.w));
    *(float4*)&out[base] = o0;
    *(float4*)&out[base + 4] = o1;
}

__global__ __launch_bounds__(256)
void wt_transpose(const float* __restrict__ Wq,
                  const float* __restrict__ Wk,
                  const float* __restrict__ Wv) {
    __shared__ float t[64][65];
    const int tid = threadIdx.x;
    const int et = blockIdx.x;
    const int h  = blockIdx.y;
    const int mat = blockIdx.z;
    const float* W = (mat == 0) ? Wq : (mat == 1) ? Wk : Wv;
    const float* src = W + (size_t)h * (EMB * HS) + (size_t)(et * 64) * HS;
    float* out = g_wt + (size_t)mat * (EMB * EMB);

    for (int i = tid; i < 64 * 64; i += 256) {
        int e = i >> 6, d = i & 63;
        t[e][d] = src[(size_t)e * HS + d];
    }
    __syncthreads();
    for (int i = tid; i < 64 * 64; i += 256) {
        int d = i >> 6, e = i & 63;
        out[(size_t)(h * 64 + d) * EMB + et * 64 + perm8(e)] = tf32_rna(t[e][d]);
    }
}

// ---------------------------------------------------------------------------
// tf32 mma.sync GEMM core (R10 structure: 2-stage, 2 CTAs/SM), with
// strength-reduced loaders: per-thread pointers/offsets hoisted out of the
// chunk loop.
// ---------------------------------------------------------------------------
#define LDF 40
#define TILE_F (128 * LDF)
#define BUF_BYTES (2 * TILE_F * 4)          // A+B one stage = 40960
#define MMA_SMEM_BYTES (2 * BUF_BYTES)      // 81920 -> 2 CTAs/SM
#define NCHUNK (EMB / 32)

__device__ __forceinline__ void gemm_mainloop(char* smraw, uint32_t base,
                                              const float* __restrict__ Ag,
                                              const float* __restrict__ Bg,
                                              int m0, int n0,
                                              float acc[4][4][4]) {
    const int tid = threadIdx.x;
    const int wid = tid >> 5, lane = tid & 31;
    const int wm = wid & 1, wn = wid >> 1;
    const int r4 = lane >> 2, c4 = lane & 3;

    // Hoisted loader addressing: 4 (row, c) slots per operand, fixed per thread.
    const float* apt[4];
    const float* bpt[4];
    uint32_t sofs[4];
#pragma unroll
    for (int i = 0; i < 4; ++i) {
        int idx = i * 256 + tid;
        int row = idx >> 3, c = idx & 7;
        apt[i] = Ag + (size_t)(m0 + row) * EMB + c * 4;
        bpt[i] = Bg + (size_t)(n0 + row) * EMB + c * 4;
        sofs[i] = base + (uint32_t)(row * (LDF * 4) + c * 16);
    }

#define GEMM_LOAD(buf, kc) do {                                              \
    uint32_t _b = (uint32_t)(buf) * BUF_BYTES;                               \
    int _k = (kc) * 32;                                                      \
    _Pragma("unroll")                                                        \
    for (int _i = 0; _i < 4; ++_i)                                           \
        CP_ASYNC16(sofs[_i] + _b, apt[_i] + _k);                             \
    _Pragma("unroll")                                                        \
    for (int _i = 0; _i < 4; ++_i)                                           \
        CP_ASYNC16(sofs[_i] + _b + TILE_F * 4, bpt[_i] + _k);                \
    CP_COMMIT();                                                             \
} while (0)

    GEMM_LOAD(0, 0);
    GEMM_LOAD(1, 1);

    // Hoisted fragment smem bases (compute-side LDS).
    const int a_fr = (wm * 64 + r4) * LDF + 2 * c4;
    const int b_fr = (wn * 32 + r4) * LDF + 2 * c4;

    for (int kc = 0; kc < NCHUNK; ++kc) {
        if (kc + 1 < NCHUNK) { CP_WAIT(1); } else { CP_WAIT(0); }
        __syncthreads();

        const float* As = (const float*)(smraw + (size_t)(kc & 1) * BUF_BYTES);
        const float* Bs = As + TILE_F;

#pragma unroll
        for (int ks = 0; ks < 4; ++ks) {
            const int k0 = ks * 8;
            uint32_t af[4][4], bf[4][2];
#pragma unroll
            for (int mt = 0; mt < 4; ++mt) {
                int rb = a_fr + mt * 16 * LDF + k0;
                float2 u = *(const float2*)&As[rb];
                float2 w = *(const float2*)&As[rb + 8 * LDF];
                af[mt][0] = __float_as_uint(u.x);
                af[mt][1] = __float_as_uint(w.x);
                af[mt][2] = __float_as_uint(u.y);
                af[mt][3] = __float_as_uint(w.y);
            }
#pragma unroll
            for (int nt = 0; nt < 4; ++nt) {
                int nb = b_fr + nt * 8 * LDF + k0;
                float2 u = *(const float2*)&Bs[nb];
                bf[nt][0] = __float_as_uint(u.x);
                bf[nt][1] = __float_as_uint(u.y);
            }
#pragma unroll
            for (int mt = 0; mt < 4; ++mt)
#pragma unroll
                for (int nt = 0; nt < 4; ++nt)
                    mma_tf32(acc[mt][nt], af[mt], bf[nt]);
        }
        __syncthreads();
        if (kc + 2 < NCHUNK)
            GEMM_LOAD(kc & 1, kc + 2);
    }
#undef GEMM_LOAD
}

// ---------------------------------------------------------------------------
// Kernel 1: QKV projection (R10 epilogue: bf16-packed Q/K, tf32 V^T tiles).
// ---------------------------------------------------------------------------
__global__ __launch_bounds__(256, 2)
void qkv_mma(void) {
    extern __shared__ char sm[];
    uint32_t base = smem_u32(sm);
    const int tid = threadIdx.x;
    const int wid = tid >> 5, lane = tid & 31;
    const int wm = wid & 1, wn = wid >> 1;
    const int r4 = lane >> 2, c4 = lane & 3;
    const int mat = blockIdx.x >> 3;
    const int n0 = (blockIdx.x & 7) * 128;
    const int m0 = blockIdx.y * 128;
    const float* Bg = g_wt + (size_t)mat * (EMB * EMB);

    float acc[4][4][4] = {};
    gemm_mainloop(sm, base, g_xr, Bg, m0, n0, acc);

    const float qscale = (mat == 0) ? 0.125f : 1.0f;
#pragma unroll
    for (int mt = 0; mt < 4; ++mt) {
#pragma unroll
        for (int nt = 0; nt < 4; ++nt) {
            int n = n0 + wn * 32 + nt * 8 + c4 * 2;
            int h_ = n >> 6, d_ = n & 63;
#pragma unroll
            for (int rr = 0; rr < 2; ++rr) {
                int m = m0 + wm * 64 + mt * 16 + r4 + rr * 8;
                int b_ = m >> 10, s_ = m & 1023;
                float vx = acc[mt][nt][rr * 2];
                float vy = acc[mt][nt][rr * 2 + 1];
                if (mat == 2) {
                    // V: [bh][tile][d][t]  tf32, plain transpose
                    size_t tb = ((size_t)(b_ * NH + h_) * 16 + (s_ >> 6)) * 4096;
                    int t_ = s_ & 63;
                    g_v[tb + (size_t)d_ * 64 + t_] = tf32_rna(vx);
                    g_v[tb + (size_t)(d_ + 1) * 64 + t_] = tf32_rna(vy);
                } else {
                    // Q/K: bf16 hi/lo pair-packed row of 64 uint32
                    size_t bhs = ((size_t)(b_ * NH + h_) * SEQ + s_);
                    uint2 pk = bf16_split_pack(vx * qscale, vy * qscale);
                    int p = d_ >> 1;
                    int b8 = p >> 3, pb = p & 7;
                    int u = b8 * 16 + (pb & 3) * 4 + ((pb >> 2) << 1);
                    uint32_t* dst = (mat == 0) ? g_qu : g_ku;
                    *(uint2*)&dst[bhs * 64 + u] = pk;
                }
            }
        }
    }
}

// ---------------------------------------------------------------------------
// Kernel 3: output projection.
// ---------------------------------------------------------------------------
__global__ __launch_bounds__(256, 2)
void proj_mma(const float* __restrict__ bias, float* __restrict__ out) {
    extern __shared__ char sm[];
    uint32_t base = smem_u32(sm);
    const int tid = threadIdx.x;
    const int wid = tid >> 5, lane = tid & 31;
    const int wm = wid & 1, wn = wid >> 1;
    const int r4 = lane >> 2, c4 = lane & 3;
    const int n0 = blockIdx.x * 128;
    const int m0 = blockIdx.y * 128;

    float acc[4][4][4] = {};
    gemm_mainloop(sm, base, g_att, g_wpr, m0, n0, acc);

#pragma unroll
    for (int mt = 0; mt < 4; ++mt) {
#pragma unroll
        for (int nt = 0; nt < 4; ++nt) {
            int n = n0 + wn * 32 + nt * 8 + c4 * 2;
            float2 bv = *(const float2*)&bias[n];
#pragma unroll
            for (int rr = 0; rr < 2; ++rr) {
                int m = m0 + wm * 64 + mt * 16 + r4 + rr * 8;
                float2 v = make_float2(acc[mt][nt][rr * 2] + bv.x,
                                       acc[mt][nt][rr * 2 + 1] + bv.y);
                *(float2*)&out[(size_t)m * EMB + n] = v;
            }
        }
    }
}

// ---------------------------------------------------------------------------
// Kernel 2: causal flash attention (R10 v5), loaders strength-reduced.
// ---------------------------------------------------------------------------
#define QLU 80
#define VLD 72
#define ATTN_SMEM_BYTES ((128 * QLU + 3 * 64 * QLU) * 4 + 3 * 64 * VLD * 4)  // 157,696

__global__ __launch_bounds__(256)
void attn_mma() {
    extern __shared__ uint32_t su[];
    uint32_t* Qi = su;
    uint32_t* Kb = Qi + 128 * QLU;
    float* Vbf = (float*)(Kb + 3 * 64 * QLU);

    const int tid = threadIdx.x;
    const int w = tid >> 5, lane = tid & 31;
    const int r4 = lane >> 2, c4 = lane & 3;
    const int qt = 7 - blockIdx.x;
    const int bh = blockIdx.y;

    const uint32_t* qsrc = g_qu + ((size_t)bh * SEQ + (size_t)qt * 128) * 64;
    const uint32_t* ksrc = g_ku + (size_t)bh * SEQ * 64;
    const float* vsrc = g_v + (size_t)bh * SEQ * HS;

    uint32_t q_s = smem_u32(Qi);
    uint32_t k_s = smem_u32(Kb);
    uint32_t v_s = smem_u32(Vbf);

    // Q load: 128 rows x 64 uint32 = 2048 x 16B
#pragma unroll
    for (int i = 0; i < 8; ++i) {
        int idx = i * 256 + tid;
        int row = idx >> 4, c = idx & 15;
        CP_ASYNC16(q_s + (row * QLU + c * 4) * 4, qsrc + row * 64 + c * 4);
    }
    CP_COMMIT();

    // Hoisted K/V loader addressing (4 slots each; row/c fixed per thread).
    const uint32_t* kpt[4];
    const float* vpt[4];
    uint32_t ksm[4], vsm[4];
#pragma unroll
    for (int i = 0; i < 4; ++i) {
        int idx = i * 256 + tid;
        int row = idx >> 4, c = idx & 15;
        kpt[i] = ksrc + row * 64 + c * 4;
        vpt[i] = vsrc + row * 64 + c * 4;
        ksm[i] = k_s + (uint32_t)(row * QLU + c * 4) * 4;
        vsm[i] = v_s + (uint32_t)(row * VLD + c * 4) * 4;
    }

#define ATTN_LOAD(buf, jt) do {                                              \
    uint32_t _kb = (uint32_t)(buf) * (64 * QLU * 4);                         \
    uint32_t _vb = (uint32_t)(buf) * (64 * VLD * 4);                         \
    int _o = (jt) * 4096;                                                    \
    _Pragma("unroll")                                                        \
    for (int _i = 0; _i < 4; ++_i)                                           \
        CP_ASYNC16(ksm[_i] + _kb, kpt[_i] + _o);                             \
    _Pragma("unroll")                                                        \
    for (int _i = 0; _i < 4; ++_i)                                           \
        CP_ASYNC16(vsm[_i] + _vb, vpt[_i] + _o);                             \
    CP_COMMIT();                                                             \
} while (0)

    const int jmax = 2 * qt + 1;
    ATTN_LOAD(0, 0);
    ATTN_LOAD(1, 1);

    float m0 = -1e30f, m1 = -1e30f, l0 = 0.0f, l1 = 0.0f;
    float ot[4][2][4] = {};

    for (int jt = 0; jt <= jmax; ++jt) {
        if (jt + 1 <= jmax) { CP_WAIT(1); } else { CP_WAIT(0); }
        __syncthreads();
        if (jt + 2 <= jmax)
            ATTN_LOAD((jt + 2) % 3, jt + 2);

        const int buf = jt % 3;
        const uint32_t* Ki = Kb + buf * 64 * QLU;
        const float* Vs = Vbf + buf * 64 * VLD;

        const bool active = (jt * 64 <= qt * 128 + w * 16 + 15);
        if (active) {
            float sacc[8][4] = {};
#pragma unroll
            for (int kb = 0; kb < 4; ++kb) {
                int ra = (w * 16 + r4) * QLU + kb * 16 + c4 * 4;
                uint4 q0 = *(const uint4*)&Qi[ra];
                uint4 q1 = *(const uint4*)&Qi[ra + 8 * QLU];
                uint32_t Ah[4] = {q0.x, q1.x, q0.z, q1.z};
                uint32_t Al[4] = {q0.y, q1.y, q0.w, q1.w};
#pragma unroll
                for (int nt = 0; nt < 8; ++nt) {
                    uint4 kv = *(const uint4*)&Ki[(nt * 8 + r4) * QLU + kb * 16 + c4 * 4];
                    uint32_t Bh[2] = {kv.x, kv.z};
                    uint32_t Bl[2] = {kv.y, kv.w};
                    mma_bf16(sacc[nt], Ah, Bh);
                    mma_bf16(sacc[nt], Ah, Bl);
                    mma_bf16(sacc[nt], Al, Bh);
                }
            }

            if (jt >= 2 * qt) {
                int rg0 = qt * 128 + w * 16 + r4;
#pragma unroll
                for (int nt = 0; nt < 8; ++nt) {
                    int cg = jt * 64 + nt * 8 + c4 * 2;
                    if (cg > rg0)         sacc[nt][0] = -1e30f;
                    if (cg + 1 > rg0)     sacc[nt][1] = -1e30f;
                    if (cg > rg0 + 8)     sacc[nt][2] = -1e30f;
                    if (cg + 1 > rg0 + 8) sacc[nt][3] = -1e30f;
                }
            }

            float mx0 = m0, mx1 = m1;
#pragma unroll
            for (int nt = 0; nt < 8; ++nt) {
                mx0 = fmaxf(mx0, fmaxf(sacc[nt][0], sacc[nt][1]));
                mx1 = fmaxf(mx1, fmaxf(sacc[nt][2], sacc[nt][3]));
            }
            mx0 = fmaxf(mx0, __shfl_xor_sync(0xFFFFFFFFu, mx0, 1));
            mx0 = fmaxf(mx0, __shfl_xor_sync(0xFFFFFFFFu, mx0, 2));
            mx1 = fmaxf(mx1, __shfl_xor_sync(0xFFFFFFFFu, mx1, 1));
            mx1 = fmaxf(mx1, __shfl_xor_sync(0xFFFFFFFFu, mx1, 2));
            float a0 = __expf(m0 - mx0);
            float a1 = __expf(m1 - mx1);
            m0 = mx0; m1 = mx1;

            float s0 = 0.0f, s1 = 0.0f;
#pragma unroll
            for (int nt = 0; nt < 8; ++nt) {
                float p00 = tf32_rna(__expf(sacc[nt][0] - mx0));
                float p01 = tf32_rna(__expf(sacc[nt][1] - mx0));
                float p10 = tf32_rna(__expf(sacc[nt][2] - mx1));
                float p11 = tf32_rna(__expf(sacc[nt][3] - mx1));
                s0 += p00 + p01;
                s1 += p10 + p11;
                sacc[nt][0] = p00; sacc[nt][1] = p01;
                sacc[nt][2] = p10; sacc[nt][3] = p11;
            }
            s0 += __shfl_xor_sync(0xFFFFFFFFu, s0, 1);
            s0 += __shfl_xor_sync(0xFFFFFFFFu, s0, 2);
            s1 += __shfl_xor_sync(0xFFFFFFFFu, s1, 1);
            s1 += __shfl_xor_sync(0xFFFFFFFFu, s1, 2);
            l0 = l0 * a0 + s0;
            l1 = l1 * a1 + s1;

            float aq00 = __shfl_sync(0xFFFFFFFFu, a0, (2 * c4) * 4);
            float aq01 = __shfl_sync(0xFFFFFFFFu, a0, (2 * c4 + 1) * 4);
            float aq10 = __shfl_sync(0xFFFFFFFFu, a1, (2 * c4) * 4);
            float aq11 = __shfl_sync(0xFFFFFFFFu, a1, (2 * c4 + 1) * 4);
#pragma unroll
            for (int db = 0; db < 4; ++db) {
                ot[db][0][0] *= aq00; ot[db][0][1] *= aq01;
                ot[db][0][2] *= aq00; ot[db][0][3] *= aq01;
                ot[db][1][0] *= aq10; ot[db][1][1] *= aq11;
                ot[db][1][2] *= aq10; ot[db][1][3] *= aq11;
            }

#pragma unroll
            for (int g = 0; g < 8; ++g) {
                uint32_t bf0[2] = {__float_as_uint(sacc[g][0]), __float_as_uint(sacc[g][1])};
                uint32_t bf1[2] = {__float_as_uint(sacc[g][2]), __float_as_uint(sacc[g][3])};
#pragma unroll
                for (int db = 0; db < 4; ++db) {
                    int ra = (db * 16 + r4) * VLD + g * 8 + 2 * c4;
                    float2 u = *(const float2*)&Vs[ra];
                    float2 w2 = *(const float2*)&Vs[ra + 8 * VLD];
                    uint32_t af[4] = {__float_as_uint(u.x), __float_as_uint(w2.x),
                                      __float_as_uint(u.y), __float_as_uint(w2.y)};
                    mma_tf32(ot[db][0], af, bf0);
                    mma_tf32(ot[db][1], af, bf1);
                }
            }
        }
    }
#undef ATTN_LOAD

    // Epilogue: O = (O^T)^T / l, tf32-round, write g_att (cols perm8'd).
    const int b_ = bh >> 4, h_ = bh & 15;
    float lq00 = __shfl_sync(0xFFFFFFFFu, l0, (2 * c4) * 4);
    float lq01 = __shfl_sync(0xFFFFFFFFu, l0, (2 * c4 + 1) * 4);
    float lq10 = __shfl_sync(0xFFFFFFFFu, l1, (2 * c4) * 4);
    float lq11 = __shfl_sync(0xFFFFFFFFu, l1, (2 * c4 + 1) * 4);
    float iv[2][2] = {{1.0f / lq00, 1.0f / lq01}, {1.0f / lq10, 1.0f / lq11}};
    const int doff = (r4 & 4) ? 2 * (r4 & 3) + 1 : 2 * r4;
#pragma unroll
    for (int db = 0; db < 4; ++db) {
        int p0 = db * 16 + doff;
        int p8 = db * 16 + 8 + doff;
#pragma unroll
        for (int qh = 0; qh < 2; ++qh) {
            int q0 = qt * 128 + w * 16 + qh * 8 + 2 * c4;
            size_t row0 = (((size_t)b_ * SEQ + q0) * NH + h_) * (size_t)HS;
            size_t row1 = (((size_t)b_ * SEQ + q0 + 1) * NH + h_) * (size_t)HS;
            g_att[row0 + p0] = tf32_rna(ot[db][qh][0] * iv[qh][0]);
            g_att[row1 + p0] = tf32_rna(ot[db][qh][1] * iv[qh][1]);
            g_att[row0 + p8] = tf32_rna(ot[db][qh][2] * iv[qh][0]);
            g_att[row1 + p8] = tf32_rna(ot[db][qh][3] * iv[qh][1]);
        }
    }
}

// ---------------------------------------------------------------------------
extern "C" void kernel_launch(void* const* d_in, const int* in_sizes, int n_in,
                              void* d_out, int out_size) {
    (void)in_sizes; (void)n_in; (void)out_size;
    const float* x     = (const float*)d_in[0];
    const float* Wq    = (const float*)d_in[1];
    const float* Wk    = (const float*)d_in[2];
    const float* Wv    = (const float*)d_in[3];
    const float* Wproj = (const float*)d_in[4];
    const float* bproj = (const float*)d_in[5];
    float* out = (float*)d_out;

    cudaFuncSetAttribute(qkv_mma, cudaFuncAttributeMaxDynamicSharedMemorySize, MMA_SMEM_BYTES);
    cudaFuncSetAttribute(proj_mma, cudaFuncAttributeMaxDynamicSharedMemorySize, MMA_SMEM_BYTES);
    cudaFuncSetAttribute(attn_mma, cudaFuncAttributeMaxDynamicSharedMemorySize, ATTN_SMEM_BYTES);

    float* p_xr = nullptr;  cudaGetSymbolAddress((void**)&p_xr, g_xr);
    float* p_wpr = nullptr; cudaGetSymbolAddress((void**)&p_wpr, g_wpr);

    round_perm_kernel<<<M_TOT * EMB / 8 / 256, 256>>>(x, p_xr);
    round_perm_kernel<<<EMB * EMB / 8 / 256, 256>>>(Wproj, p_wpr);
    wt_transpose<<<dim3(16, 16, 3), 256>>>(Wq, Wk, Wv);
    qkv_mma<<<dim3(24, 64), 256, MMA_SMEM_BYTES>>>();
    attn_mma<<<dim3(8, Bsz * NH), 256, ATTN_SMEM_BYTES>>>();
    proj_mma<<<dim3(8, 64), 256, MMA_SMEM_BYTES>>>(bproj, out);
}

// round 17
// speedup vs baseline: 1.3907x; 1.0138x over previous
#include <cuda_runtime.h>
#include <cuda_bf16.h>
#include <math.h>
#include <stdint.h>

// Problem constants
#define Bsz 8
#define SEQ 1024
#define EMB 1024
#define NH  16
#define HS  64
#define M_TOT (Bsz * SEQ)   // 8192

// Scratch layouts (R10/R15):
//  g_qu, g_ku : [BH][S][64 uint32] bf16 hi/lo pair-packed rows (Q pre-scaled)
//  g_v       : [BH][tile jt][d][t]  V transposed per 64-token tile, tf32-rna'd
//  g_att     : [B,S,H*HS] cols perm8'd within 8-groups (proj A-frags)
//  g_xr/g_wt/g_wpr : perm8'd tf32 GEMM operands
__device__ uint32_t g_qu[Bsz * NH * SEQ * 64];
__device__ uint32_t g_ku[Bsz * NH * SEQ * 64];
__device__ float g_v[Bsz * NH * SEQ * HS];
__device__ float g_att[M_TOT * EMB];
__device__ float g_wt[3 * EMB * EMB];
__device__ float g_xr[M_TOT * EMB];
__device__ float g_wpr[EMB * EMB];

// ---------------------------------------------------------------------------
// Helpers
// ---------------------------------------------------------------------------
__device__ __forceinline__ uint32_t smem_u32(const void* p) {
    uint32_t a;
    asm("{ .reg .u64 t; cvta.to.shared.u64 t, %1; cvt.u32.u64 %0, t; }" : "=r"(a) : "l"(p));
    return a;
}
__device__ __forceinline__ float tf32_rna(float x) {
    uint32_t u;
    asm("cvt.rna.tf32.f32 %0, %1;" : "=r"(u) : "f"(x));
    return __uint_as_float(u);
}
__device__ __forceinline__ int perm8(int t) {   // pair-permute within 8-group
    int r = t & 7;
    return (t & ~7) + ((r & 4) ? 2 * (r & 3) + 1 : 2 * r);
}
// Split (x,y) into bf16 hi/lo pairs: {hi_pack, lo_pack}, low half = x.
__device__ __forceinline__ uint2 bf16_split_pack(float x, float y) {
    __nv_bfloat16 hx = __float2bfloat16(x);
    __nv_bfloat16 hy = __float2bfloat16(y);
    float lx = x - __bfloat162float(hx);
    float ly = y - __bfloat162float(hy);
    __nv_bfloat162 hp = __halves2bfloat162(hx, hy);
    __nv_bfloat162 lp = __halves2bfloat162(__float2bfloat16(lx), __float2bfloat16(ly));
    uint2 r;
    r.x = *(uint32_t*)&hp;
    r.y = *(uint32_t*)&lp;
    return r;
}
#define CP_ASYNC16(dst, src) \
    asm volatile("cp.async.cg.shared.global [%0], [%1], 16;" :: "r"(dst), "l"(src))
#define CP_COMMIT() asm volatile("cp.async.commit_group;" ::: "memory")
#define CP_WAIT(n)  asm volatile("cp.async.wait_group %0;" :: "n"(n) : "memory")

__device__ __forceinline__ void mma_tf32(float* d, const uint32_t* a, const uint32_t* b) {
    asm volatile(
        "mma.sync.aligned.m16n8k8.row.col.f32.tf32.tf32.f32 "
        "{%0,%1,%2,%3}, {%4,%5,%6,%7}, {%8,%9}, {%0,%1,%2,%3};"
        : "+f"(d[0]), "+f"(d[1]), "+f"(d[2]), "+f"(d[3])
        : "r"(a[0]), "r"(a[1]), "r"(a[2]), "r"(a[3]), "r"(b[0]), "r"(b[1]));
}
__device__ __forceinline__ void mma_bf16(float* d, const uint32_t* a, const uint32_t* b) {
    asm volatile(
        "mma.sync.aligned.m16n8k16.row.col.f32.bf16.bf16.f32 "
        "{%0,%1,%2,%3}, {%4,%5,%6,%7}, {%8,%9}, {%0,%1,%2,%3};"
        : "+f"(d[0]), "+f"(d[1]), "+f"(d[2]), "+f"(d[3])
        : "r"(a[0]), "r"(a[1]), "r"(a[2]), "r"(a[3]), "r"(b[0]), "r"(b[1]));
}

// ---------------------------------------------------------------------------
// Prep kernels (unchanged)
// ---------------------------------------------------------------------------
__global__ __launch_bounds__(256)
void round_perm_kernel(const float* __restrict__ in, float* __restrict__ out) {
    size_t g = (size_t)blockIdx.x * 256 + threadIdx.x;
    size_t base = g * 8;
    float4 a = *(const float4*)&in[base];
    float4 b = *(const float4*)&in[base + 4];
    float4 o0 = make_float4(tf32_rna(a.x), tf32_rna(b.x), tf32_rna(a.y), tf32_rna(b.y));
    float4 o1 = make_float4(tf32_rna(a.z), tf32_rna(b.z), tf32_rna(a.w), tf32_rna(b.w));
    *(float4*)&out[base] = o0;
    *(float4*)&out[base + 4] = o1;
}

__global__ __launch_bounds__(256)
void wt_transpose(const float* __restrict__ Wq,
                  const float* __restrict__ Wk,
                  const float* __restrict__ Wv) {
    __shared__ float t[64][65];
    const int tid = threadIdx.x;
    const int et = blockIdx.x;
    const int h  = blockIdx.y;
    const int mat = blockIdx.z;
    const float* W = (mat == 0) ? Wq : (mat == 1) ? Wk : Wv;
    const float* src = W + (size_t)h * (EMB * HS) + (size_t)(et * 64) * HS;
    float* out = g_wt + (size_t)mat * (EMB * EMB);

    for (int i = tid; i < 64 * 64; i += 256) {
        int e = i >> 6, d = i & 63;
        t[e][d] = src[(size_t)e * HS + d];
    }
    __syncthreads();
    for (int i = tid; i < 64 * 64; i += 256) {
        int d = i >> 6, e = i & 63;
        out[(size_t)(h * 64 + d) * EMB + et * 64 + perm8(e)] = tf32_rna(t[e][d]);
    }
}

// ---------------------------------------------------------------------------
// tf32 mma.sync GEMM core v3: 128 threads = 4 warps (2m x 2n), warp tile
// 64x64, block tile 128x128, 2-stage, 2 CTAs/SM. LDS:MMA ratio 0.5.
// ---------------------------------------------------------------------------
#define LDF 40
#define TILE_F (128 * LDF)
#define BUF_BYTES (2 * TILE_F * 4)          // A+B one stage = 40960
#define MMA_SMEM_BYTES (2 * BUF_BYTES)      // 81920 -> 2 CTAs/SM
#define NCHUNK (EMB / 32)

__device__ __forceinline__ void gemm_mainloop(char* smraw, uint32_t base,
                                              const float* __restrict__ Ag,
                                              const float* __restrict__ Bg,
                                              int m0, int n0,
                                              float acc[4][8][4]) {
    const int tid = threadIdx.x;
    const int wid = tid >> 5, lane = tid & 31;
    const int wm = wid & 1, wn = wid >> 1;
    const int r4 = lane >> 2, c4 = lane & 3;

    // Loader bases (row stride per i is compile-time: 16 rows).
    const int lrow = tid >> 3, lc = tid & 7;       // lrow 0..15, lc 0..7
    const float* ap0 = Ag + (size_t)(m0 + lrow) * EMB + lc * 4;
    const float* bp0 = Bg + (size_t)(n0 + lrow) * EMB + lc * 4;
    const uint32_t s0 = base + (uint32_t)(lrow * (LDF * 4) + lc * 16);

#define GEMM_LOAD(buf, kc) do {                                              \
    uint32_t _b = (uint32_t)(buf) * BUF_BYTES;                               \
    int _k = (kc) * 32;                                                      \
    _Pragma("unroll")                                                        \
    for (int _i = 0; _i < 8; ++_i)                                           \
        CP_ASYNC16(s0 + _b + _i * (16 * LDF * 4), ap0 + _i * (16 * EMB) + _k); \
    _Pragma("unroll")                                                        \
    for (int _i = 0; _i < 8; ++_i)                                           \
        CP_ASYNC16(s0 + _b + TILE_F * 4 + _i * (16 * LDF * 4),               \
                   bp0 + _i * (16 * EMB) + _k);                              \
    CP_COMMIT();                                                             \
} while (0)

    GEMM_LOAD(0, 0);
    GEMM_LOAD(1, 1);

    const int a_fr = (wm * 64 + r4) * LDF + 2 * c4;
    const int b_fr = (wn * 64 + r4) * LDF + 2 * c4;

    for (int kc = 0; kc < NCHUNK; ++kc) {
        if (kc + 1 < NCHUNK) { CP_WAIT(1); } else { CP_WAIT(0); }
        __syncthreads();

        const float* As = (const float*)(smraw + (size_t)(kc & 1) * BUF_BYTES);
        const float* Bs = As + TILE_F;

#pragma unroll
        for (int ks = 0; ks < 4; ++ks) {
            const int k0 = ks * 8;
            uint32_t af[4][4], bf[8][2];
#pragma unroll
            for (int mt = 0; mt < 4; ++mt) {
                int rb = a_fr + mt * 16 * LDF + k0;
                float2 u = *(const float2*)&As[rb];
                float2 w = *(const float2*)&As[rb + 8 * LDF];
                af[mt][0] = __float_as_uint(u.x);
                af[mt][1] = __float_as_uint(w.x);
                af[mt][2] = __float_as_uint(u.y);
                af[mt][3] = __float_as_uint(w.y);
            }
#pragma unroll
            for (int nt = 0; nt < 8; ++nt) {
                int nb = b_fr + nt * 8 * LDF + k0;
                float2 u = *(const float2*)&Bs[nb];
                bf[nt][0] = __float_as_uint(u.x);
                bf[nt][1] = __float_as_uint(u.y);
            }
#pragma unroll
            for (int mt = 0; mt < 4; ++mt)
#pragma unroll
                for (int nt = 0; nt < 8; ++nt)
                    mma_tf32(acc[mt][nt], af[mt], bf[nt]);
        }
        __syncthreads();
        if (kc + 2 < NCHUNK)
            GEMM_LOAD(kc & 1, kc + 2);
    }
#undef GEMM_LOAD
}

// ---------------------------------------------------------------------------
// Kernel 1: QKV projection (epilogue: bf16-packed Q/K, tf32 V^T tiles).
// ---------------------------------------------------------------------------
__global__ __launch_bounds__(128, 2)
void qkv_mma(void) {
    extern __shared__ char sm[];
    uint32_t base = smem_u32(sm);
    const int tid = threadIdx.x;
    const int wid = tid >> 5, lane = tid & 31;
    const int wm = wid & 1, wn = wid >> 1;
    const int r4 = lane >> 2, c4 = lane & 3;
    const int mat = blockIdx.x >> 3;
    const int n0 = (blockIdx.x & 7) * 128;
    const int m0 = blockIdx.y * 128;
    const float* Bg = g_wt + (size_t)mat * (EMB * EMB);

    float acc[4][8][4] = {};
    gemm_mainloop(sm, base, g_xr, Bg, m0, n0, acc);

    const float qscale = (mat == 0) ? 0.125f : 1.0f;
#pragma unroll
    for (int mt = 0; mt < 4; ++mt) {
#pragma unroll
        for (int nt = 0; nt < 8; ++nt) {
            int n = n0 + wn * 64 + nt * 8 + c4 * 2;
            int h_ = n >> 6, d_ = n & 63;
#pragma unroll
            for (int rr = 0; rr < 2; ++rr) {
                int m = m0 + wm * 64 + mt * 16 + r4 + rr * 8;
                int b_ = m >> 10, s_ = m & 1023;
                float vx = acc[mt][nt][rr * 2];
                float vy = acc[mt][nt][rr * 2 + 1];
                if (mat == 2) {
                    // V: [bh][tile][d][t]  tf32, plain transpose
                    size_t tb = ((size_t)(b_ * NH + h_) * 16 + (s_ >> 6)) * 4096;
                    int t_ = s_ & 63;
                    g_v[tb + (size_t)d_ * 64 + t_] = tf32_rna(vx);
                    g_v[tb + (size_t)(d_ + 1) * 64 + t_] = tf32_rna(vy);
                } else {
                    // Q/K: bf16 hi/lo pair-packed row of 64 uint32
                    size_t bhs = ((size_t)(b_ * NH + h_) * SEQ + s_);
                    uint2 pk = bf16_split_pack(vx * qscale, vy * qscale);
                    int p = d_ >> 1;
                    int b8 = p >> 3, pb = p & 7;
                    int u = b8 * 16 + (pb & 3) * 4 + ((pb >> 2) << 1);
                    uint32_t* dst = (mat == 0) ? g_qu : g_ku;
                    *(uint2*)&dst[bhs * 64 + u] = pk;
                }
            }
        }
    }
}

// ---------------------------------------------------------------------------
// Kernel 3: output projection.
// ---------------------------------------------------------------------------
__global__ __launch_bounds__(128, 2)
void proj_mma(const float* __restrict__ bias, float* __restrict__ out) {
    extern __shared__ char sm[];
    uint32_t base = smem_u32(sm);
    const int tid = threadIdx.x;
    const int wid = tid >> 5, lane = tid & 31;
    const int wm = wid & 1, wn = wid >> 1;
    const int r4 = lane >> 2, c4 = lane & 3;
    const int n0 = blockIdx.x * 128;
    const int m0 = blockIdx.y * 128;

    float acc[4][8][4] = {};
    gemm_mainloop(sm, base, g_att, g_wpr, m0, n0, acc);

#pragma unroll
    for (int mt = 0; mt < 4; ++mt) {
#pragma unroll
        for (int nt = 0; nt < 8; ++nt) {
            int n = n0 + wn * 64 + nt * 8 + c4 * 2;
            float2 bv = *(const float2*)&bias[n];
#pragma unroll
            for (int rr = 0; rr < 2; ++rr) {
                int m = m0 + wm * 64 + mt * 16 + r4 + rr * 8;
                float2 v = make_float2(acc[mt][nt][rr * 2] + bv.x,
                                       acc[mt][nt][rr * 2 + 1] + bv.y);
                *(float2*)&out[(size_t)m * EMB + n] = v;
            }
        }
    }
}

// ---------------------------------------------------------------------------
// Kernel 2: causal flash attention (R15, unchanged).
// ---------------------------------------------------------------------------
#define QLU 80
#define VLD 72
#define ATTN_SMEM_BYTES ((128 * QLU + 3 * 64 * QLU) * 4 + 3 * 64 * VLD * 4)  // 157,696

__global__ __launch_bounds__(256)
void attn_mma() {
    extern __shared__ uint32_t su[];
    uint32_t* Qi = su;
    uint32_t* Kb = Qi + 128 * QLU;
    float* Vbf = (float*)(Kb + 3 * 64 * QLU);

    const int tid = threadIdx.x;
    const int w = tid >> 5, lane = tid & 31;
    const int r4 = lane >> 2, c4 = lane & 3;
    const int qt = 7 - blockIdx.x;
    const int bh = blockIdx.y;

    const uint32_t* qsrc = g_qu + ((size_t)bh * SEQ + (size_t)qt * 128) * 64;
    const uint32_t* ksrc = g_ku + (size_t)bh * SEQ * 64;
    const float* vsrc = g_v + (size_t)bh * SEQ * HS;

    uint32_t q_s = smem_u32(Qi);
    uint32_t k_s = smem_u32(Kb);
    uint32_t v_s = smem_u32(Vbf);

#pragma unroll
    for (int i = 0; i < 8; ++i) {
        int idx = i * 256 + tid;
        int row = idx >> 4, c = idx & 15;
        CP_ASYNC16(q_s + (row * QLU + c * 4) * 4, qsrc + row * 64 + c * 4);
    }
    CP_COMMIT();

    const uint32_t* kpt[4];
    const float* vpt[4];
    uint32_t ksm[4], vsm[4];
#pragma unroll
    for (int i = 0; i < 4; ++i) {
        int idx = i * 256 + tid;
        int row = idx >> 4, c = idx & 15;
        kpt[i] = ksrc + row * 64 + c * 4;
        vpt[i] = vsrc + row * 64 + c * 4;
        ksm[i] = k_s + (uint32_t)(row * QLU + c * 4) * 4;
        vsm[i] = v_s + (uint32_t)(row * VLD + c * 4) * 4;
    }

#define ATTN_LOAD(buf, jt) do {                                              \
    uint32_t _kb = (uint32_t)(buf) * (64 * QLU * 4);                         \
    uint32_t _vb = (uint32_t)(buf) * (64 * VLD * 4);                         \
    int _o = (jt) * 4096;                                                    \
    _Pragma("unroll")                                                        \
    for (int _i = 0; _i < 4; ++_i)                                           \
        CP_ASYNC16(ksm[_i] + _kb, kpt[_i] + _o);                             \
    _Pragma("unroll")                                                        \
    for (int _i = 0; _i < 4; ++_i)                                           \
        CP_ASYNC16(vsm[_i] + _vb, vpt[_i] + _o);                             \
    CP_COMMIT();                                                             \
} while (0)

    const int jmax = 2 * qt + 1;
    ATTN_LOAD(0, 0);
    ATTN_LOAD(1, 1);

    float m0 = -1e30f, m1 = -1e30f, l0 = 0.0f, l1 = 0.0f;
    float ot[4][2][4] = {};

    for (int jt = 0; jt <= jmax; ++jt) {
        if (jt + 1 <= jmax) { CP_WAIT(1); } else { CP_WAIT(0); }
        __syncthreads();
        if (jt + 2 <= jmax)
            ATTN_LOAD((jt + 2) % 3, jt + 2);

        const int buf = jt % 3;
        const uint32_t* Ki = Kb + buf * 64 * QLU;
        const float* Vs = Vbf + buf * 64 * VLD;

        const bool active = (jt * 64 <= qt * 128 + w * 16 + 15);
        if (active) {
            float sacc[8][4] = {};
#pragma unroll
            for (int kb = 0; kb < 4; ++kb) {
                int ra = (w * 16 + r4) * QLU + kb * 16 + c4 * 4;
                uint4 q0 = *(const uint4*)&Qi[ra];
                uint4 q1 = *(const uint4*)&Qi[ra + 8 * QLU];
                uint32_t Ah[4] = {q0.x, q1.x, q0.z, q1.z};
                uint32_t Al[4] = {q0.y, q1.y, q0.w, q1.w};
#pragma unroll
                for (int nt = 0; nt < 8; ++nt) {
                    uint4 kv = *(const uint4*)&Ki[(nt * 8 + r4) * QLU + kb * 16 + c4 * 4];
                    uint32_t Bh[2] = {kv.x, kv.z};
                    uint32_t Bl[2] = {kv.y, kv.w};
                    mma_bf16(sacc[nt], Ah, Bh);
                    mma_bf16(sacc[nt], Ah, Bl);
                    mma_bf16(sacc[nt], Al, Bh);
                }
            }

            if (jt >= 2 * qt) {
                int rg0 = qt * 128 + w * 16 + r4;
#pragma unroll
                for (int nt = 0; nt < 8; ++nt) {
                    int cg = jt * 64 + nt * 8 + c4 * 2;
                    if (cg > rg0)         sacc[nt][0] = -1e30f;
                    if (cg + 1 > rg0)     sacc[nt][1] = -1e30f;
                    if (cg > rg0 + 8)     sacc[nt][2] = -1e30f;
                    if (cg + 1 > rg0 + 8) sacc[nt][3] = -1e30f;
                }
            }

            float mx0 = m0, mx1 = m1;
#pragma unroll
            for (int nt = 0; nt < 8; ++nt) {
                mx0 = fmaxf(mx0, fmaxf(sacc[nt][0], sacc[nt][1]));
                mx1 = fmaxf(mx1, fmaxf(sacc[nt][2], sacc[nt][3]));
            }
            mx0 = fmaxf(mx0, __shfl_xor_sync(0xFFFFFFFFu, mx0, 1));
            mx0 = fmaxf(mx0, __shfl_xor_sync(0xFFFFFFFFu, mx0, 2));
            mx1 = fmaxf(mx1, __shfl_xor_sync(0xFFFFFFFFu, mx1, 1));
            mx1 = fmaxf(mx1, __shfl_xor_sync(0xFFFFFFFFu, mx1, 2));
            float a0 = __expf(m0 - mx0);
            float a1 = __expf(m1 - mx1);
            m0 = mx0; m1 = mx1;

            float s0 = 0.0f, s1 = 0.0f;
#pragma unroll
            for (int nt = 0; nt < 8; ++nt) {
                float p00 = tf32_rna(__expf(sacc[nt][0] - mx0));
                float p01 = tf32_rna(__expf(sacc[nt][1] - mx0));
                float p10 = tf32_rna(__expf(sacc[nt][2] - mx1));
                float p11 = tf32_rna(__expf(sacc[nt][3] - mx1));
                s0 += p00 + p01;
                s1 += p10 + p11;
                sacc[nt][0] = p00; sacc[nt][1] = p01;
                sacc[nt][2] = p10; sacc[nt][3] = p11;
            }
            s0 += __shfl_xor_sync(0xFFFFFFFFu, s0, 1);
            s0 += __shfl_xor_sync(0xFFFFFFFFu, s0, 2);
            s1 += __shfl_xor_sync(0xFFFFFFFFu, s1, 1);
            s1 += __shfl_xor_sync(0xFFFFFFFFu, s1, 2);
            l0 = l0 * a0 + s0;
            l1 = l1 * a1 + s1;

            float aq00 = __shfl_sync(0xFFFFFFFFu, a0, (2 * c4) * 4);
            float aq01 = __shfl_sync(0xFFFFFFFFu, a0, (2 * c4 + 1) * 4);
            float aq10 = __shfl_sync(0xFFFFFFFFu, a1, (2 * c4) * 4);
            float aq11 = __shfl_sync(0xFFFFFFFFu, a1, (2 * c4 + 1) * 4);
#pragma unroll
            for (int db = 0; db < 4; ++db) {
                ot[db][0][0] *= aq00; ot[db][0][1] *= aq01;
                ot[db][0][2] *= aq00; ot[db][0][3] *= aq01;
                ot[db][1][0] *= aq10; ot[db][1][1] *= aq11;
                ot[db][1][2] *= aq10; ot[db][1][3] *= aq11;
            }

#pragma unroll
            for (int g = 0; g < 8; ++g) {
                uint32_t bf0[2] = {__float_as_uint(sacc[g][0]), __float_as_uint(sacc[g][1])};
                uint32_t bf1[2] = {__float_as_uint(sacc[g][2]), __float_as_uint(sacc[g][3])};
#pragma unroll
                for (int db = 0; db < 4; ++db) {
                    int ra = (db * 16 + r4) * VLD + g * 8 + 2 * c4;
                    float2 u = *(const float2*)&Vs[ra];
                    float2 w2 = *(const float2*)&Vs[ra + 8 * VLD];
                    uint32_t af[4] = {__float_as_uint(u.x), __float_as_uint(w2.x),
                                      __float_as_uint(u.y), __float_as_uint(w2.y)};
                    mma_tf32(ot[db][0], af, bf0);
                    mma_tf32(ot[db][1], af, bf1);
                }
            }
        }
    }
#undef ATTN_LOAD

    // Epilogue: O = (O^T)^T / l, tf32-round, write g_att (cols perm8'd).
    const int b_ = bh >> 4, h_ = bh & 15;
    float lq00 = __shfl_sync(0xFFFFFFFFu, l0, (2 * c4) * 4);
    float lq01 = __shfl_sync(0xFFFFFFFFu, l0, (2 * c4 + 1) * 4);
    float lq10 = __shfl_sync(0xFFFFFFFFu, l1, (2 * c4) * 4);
    float lq11 = __shfl_sync(0xFFFFFFFFu, l1, (2 * c4 + 1) * 4);
    float iv[2][2] = {{1.0f / lq00, 1.0f / lq01}, {1.0f / lq10, 1.0f / lq11}};
    const int doff = (r4 & 4) ? 2 * (r4 & 3) + 1 : 2 * r4;
#pragma unroll
    for (int db = 0; db < 4; ++db) {
        int p0 = db * 16 + doff;
        int p8 = db * 16 + 8 + doff;
#pragma unroll
        for (int qh = 0; qh < 2; ++qh) {
            int q0 = qt * 128 + w * 16 + qh * 8 + 2 * c4;
            size_t row0 = (((size_t)b_ * SEQ + q0) * NH + h_) * (size_t)HS;
            size_t row1 = (((size_t)b_ * SEQ + q0 + 1) * NH + h_) * (size_t)HS;
            g_att[row0 + p0] = tf32_rna(ot[db][qh][0] * iv[qh][0]);
            g_att[row1 + p0] = tf32_rna(ot[db][qh][1] * iv[qh][1]);
            g_att[row0 + p8] = tf32_rna(ot[db][qh][2] * iv[qh][0]);
            g_att[row1 + p8] = tf32_rna(ot[db][qh][3] * iv[qh][1]);
        }
    }
}

// ---------------------------------------------------------------------------
extern "C" void kernel_launch(void* const* d_in, const int* in_sizes, int n_in,
                              void* d_out, int out_size) {
    (void)in_sizes; (void)n_in; (void)out_size;
    const float* x     = (const float*)d_in[0];
    const float* Wq    = (const float*)d_in[1];
    const float* Wk    = (const float*)d_in[2];
    const float* Wv    = (const float*)d_in[3];
    const float* Wproj = (const float*)d_in[4];
    const float* bproj = (const float*)d_in[5];
    float* out = (float*)d_out;

    cudaFuncSetAttribute(qkv_mma, cudaFuncAttributeMaxDynamicSharedMemorySize, MMA_SMEM_BYTES);
    cudaFuncSetAttribute(proj_mma, cudaFuncAttributeMaxDynamicSharedMemorySize, MMA_SMEM_BYTES);
    cudaFuncSetAttribute(attn_mma, cudaFuncAttributeMaxDynamicSharedMemorySize, ATTN_SMEM_BYTES);

    float* p_xr = nullptr;  cudaGetSymbolAddress((void**)&p_xr, g_xr);
    float* p_wpr = nullptr; cudaGetSymbolAddress((void**)&p_wpr, g_wpr);

    round_perm_kernel<<<M_TOT * EMB / 8 / 256, 256>>>(x, p_xr);
    round_perm_kernel<<<EMB * EMB / 8 / 256, 256>>>(Wproj, p_wpr);
    wt_transpose<<<dim3(16, 16, 3), 256>>>(Wq, Wk, Wv);
    qkv_mma<<<dim3(24, 64), 128, MMA_SMEM_BYTES>>>();
    attn_mma<<<dim3(8, Bsz * NH), 256, ATTN_SMEM_BYTES>>>();
    proj_mma<<<dim3(8, 64), 128, MMA_SMEM_BYTES>>>(bproj, out);
}